// round 5
// baseline (speedup 1.0000x reference)
#include <cuda_runtime.h>

// ---------------- Problem constants ----------------
#define NMAX   100000
#define EMAX   3200000
#define ETOT   (EMAX + NMAX)   // edges + self loops
#define FDIM   128
#define CDIM   10
#define NGRAPH 512

// ---------------- Device scratch (static, allocation-free) ----------------
__device__ float g_h   [NMAX * FDIM];   // aggregated features (layer output)
__device__ float g_hw  [NMAX * FDIM];   // GEMM output (pre-aggregation)
__device__ float g_h10a[NMAX * CDIM];   // last-layer GEMM output
__device__ float g_h10b[NMAX * CDIM];   // last-layer aggregated
__device__ int   g_src [ETOT];
__device__ float g_norm[ETOT];
__device__ int   g_rowptr[NMAX + 1];
__device__ int   g_cursor[NMAX];
__device__ int   g_deg [NMAX];
__device__ float g_dinv[NMAX];
__device__ int   g_bsums[256];
__device__ float g_pool[NGRAPH * CDIM];
__device__ float g_cnt [NGRAPH];

// ---------------- Graph preprocessing ----------------

__global__ void k_init(int N) {
    int i = blockIdx.x * blockDim.x + threadIdx.x;
    if (i < N) g_deg[i] = 1;                    // self loop contributes 1
    if (i < NGRAPH * CDIM) g_pool[i] = 0.0f;
    if (i < NGRAPH) g_cnt[i] = 0.0f;
}

// NOTE: edge_index / batch are INT32 (JAX downcasts int64 without x64 mode).
__global__ void k_count(const int* __restrict__ ei, int E) {
    int e = blockIdx.x * blockDim.x + threadIdx.x;
    if (e >= E) return;
    int d = ei[E + e];
    atomicAdd(&g_deg[d], 1);
}

__global__ void k_dinv(int N) {
    int i = blockIdx.x * blockDim.x + threadIdx.x;
    if (i >= N) return;
    g_dinv[i] = rsqrtf((float)g_deg[i]);
}

// Per-block exclusive scan of g_deg into g_rowptr; block sums into g_bsums.
__global__ void k_scan_block(int N) {
    __shared__ int sh[1024];
    int tid = threadIdx.x;
    int i = blockIdx.x * 1024 + tid;
    int v = (i < N) ? g_deg[i] : 0;
    sh[tid] = v;
    __syncthreads();
    for (int off = 1; off < 1024; off <<= 1) {
        int t = (tid >= off) ? sh[tid - off] : 0;
        __syncthreads();
        sh[tid] += t;
        __syncthreads();
    }
    if (i < N) g_rowptr[i] = sh[tid] - v;       // exclusive within block
    if (tid == 1023) g_bsums[blockIdx.x] = sh[1023];
}

__global__ void k_scan_sums(int nb, int N) {
    if (threadIdx.x == 0 && blockIdx.x == 0) {
        int run = 0;
        for (int b = 0; b < nb; b++) { int t = g_bsums[b]; g_bsums[b] = run; run += t; }
        g_rowptr[N] = run;
    }
}

__global__ void k_scan_add(int N) {
    int i = blockIdx.x * blockDim.x + threadIdx.x;
    if (i >= N) return;
    g_rowptr[i] += g_bsums[i >> 10];
}

// Self-loop goes in slot 0 of each node's segment; cursor starts after it.
__global__ void k_selfloop(int N) {
    int i = blockIdx.x * blockDim.x + threadIdx.x;
    if (i >= N) return;
    int p = g_rowptr[i];
    float di = g_dinv[i];
    g_src[p] = i;
    g_norm[p] = di * di;
    g_cursor[i] = p + 1;
}

__global__ void k_fill(const int* __restrict__ ei, int E) {
    int e = blockIdx.x * blockDim.x + threadIdx.x;
    if (e >= E) return;
    int s = ei[e];
    int d = ei[E + e];
    int p = atomicAdd(&g_cursor[d], 1);
    g_src[p] = s;
    g_norm[p] = g_dinv[s] * g_dinv[d];
}

// ---------------- SGEMM: C[M,128] = A[M,128] @ W[128,128] ----------------
// BM=64, BN=128, BK=16, 256 threads, 4x8 thread tile.
__global__ __launch_bounds__(256) void k_gemm128(
    const float* __restrict__ A, const float* __restrict__ W,
    float* __restrict__ C, int M)
{
    __shared__ float As[16][65];    // padded (transposed) A tile
    __shared__ float Ws[16][128];
    int tid = threadIdx.x;
    int row0 = blockIdx.x * 64;
    int trow = (tid / 16) * 4;
    int tcol = (tid % 16) * 8;
    int arow = tid / 4;
    int ak   = (tid % 4) * 4;
    int wrow = tid / 32;
    int wcol = (tid % 32) * 4;

    float acc[4][8];
    #pragma unroll
    for (int i = 0; i < 4; i++)
        #pragma unroll
        for (int j = 0; j < 8; j++) acc[i][j] = 0.0f;

    for (int k0 = 0; k0 < 128; k0 += 16) {
        int gr = row0 + arow;
        float4 av = (gr < M) ? *(const float4*)&A[(long long)gr * 128 + k0 + ak]
                             : make_float4(0.f, 0.f, 0.f, 0.f);
        As[ak + 0][arow] = av.x; As[ak + 1][arow] = av.y;
        As[ak + 2][arow] = av.z; As[ak + 3][arow] = av.w;
        *(float4*)&Ws[wrow][wcol]     = *(const float4*)&W[(k0 + wrow) * 128 + wcol];
        *(float4*)&Ws[wrow + 8][wcol] = *(const float4*)&W[(k0 + wrow + 8) * 128 + wcol];
        __syncthreads();
        #pragma unroll
        for (int k = 0; k < 16; k++) {
            float a[4];
            #pragma unroll
            for (int i = 0; i < 4; i++) a[i] = As[k][trow + i];
            float b[8];
            #pragma unroll
            for (int j = 0; j < 8; j++) b[j] = Ws[k][tcol + j];
            #pragma unroll
            for (int i = 0; i < 4; i++)
                #pragma unroll
                for (int j = 0; j < 8; j++) acc[i][j] = fmaf(a[i], b[j], acc[i][j]);
        }
        __syncthreads();
    }
    #pragma unroll
    for (int i = 0; i < 4; i++) {
        int row = row0 + trow + i;
        if (row < M) {
            float4 v0 = make_float4(acc[i][0], acc[i][1], acc[i][2], acc[i][3]);
            float4 v1 = make_float4(acc[i][4], acc[i][5], acc[i][6], acc[i][7]);
            *(float4*)&C[(long long)row * 128 + tcol]     = v0;
            *(float4*)&C[(long long)row * 128 + tcol + 4] = v1;
        }
    }
}

// ---------------- Edge aggregation (pull, warp per node, D=128) ----------------
__global__ __launch_bounds__(256) void k_gather128(
    const float* __restrict__ hw, const float* __restrict__ bias,
    float* __restrict__ out, int N, int do_relu)
{
    int warp = (blockIdx.x * blockDim.x + threadIdx.x) >> 5;
    int lane = threadIdx.x & 31;
    if (warp >= N) return;
    int beg = g_rowptr[warp];
    int end = g_rowptr[warp + 1];
    float4 acc = *(const float4*)&bias[lane * 4];
    int e = beg;
    // unroll x4 for MLP
    for (; e + 4 <= end; e += 4) {
        int   s0 = g_src[e],     s1 = g_src[e + 1], s2 = g_src[e + 2], s3 = g_src[e + 3];
        float w0 = g_norm[e],    w1 = g_norm[e + 1], w2 = g_norm[e + 2], w3 = g_norm[e + 3];
        float4 v0 = *(const float4*)&hw[(long long)s0 * 128 + lane * 4];
        float4 v1 = *(const float4*)&hw[(long long)s1 * 128 + lane * 4];
        float4 v2 = *(const float4*)&hw[(long long)s2 * 128 + lane * 4];
        float4 v3 = *(const float4*)&hw[(long long)s3 * 128 + lane * 4];
        acc.x = fmaf(w0, v0.x, acc.x); acc.y = fmaf(w0, v0.y, acc.y);
        acc.z = fmaf(w0, v0.z, acc.z); acc.w = fmaf(w0, v0.w, acc.w);
        acc.x = fmaf(w1, v1.x, acc.x); acc.y = fmaf(w1, v1.y, acc.y);
        acc.z = fmaf(w1, v1.z, acc.z); acc.w = fmaf(w1, v1.w, acc.w);
        acc.x = fmaf(w2, v2.x, acc.x); acc.y = fmaf(w2, v2.y, acc.y);
        acc.z = fmaf(w2, v2.z, acc.z); acc.w = fmaf(w2, v2.w, acc.w);
        acc.x = fmaf(w3, v3.x, acc.x); acc.y = fmaf(w3, v3.y, acc.y);
        acc.z = fmaf(w3, v3.z, acc.z); acc.w = fmaf(w3, v3.w, acc.w);
    }
    for (; e < end; e++) {
        int s = g_src[e];
        float w = g_norm[e];
        float4 v = *(const float4*)&hw[(long long)s * 128 + lane * 4];
        acc.x = fmaf(w, v.x, acc.x); acc.y = fmaf(w, v.y, acc.y);
        acc.z = fmaf(w, v.z, acc.z); acc.w = fmaf(w, v.w, acc.w);
    }
    if (do_relu) {
        acc.x = fmaxf(acc.x, 0.f); acc.y = fmaxf(acc.y, 0.f);
        acc.z = fmaxf(acc.z, 0.f); acc.w = fmaxf(acc.w, 0.f);
    }
    *(float4*)&out[(long long)warp * 128 + lane * 4] = acc;
}

// ---------------- Last layer: C[M,10] = A[M,128] @ W[128,10] (warp per row) ----
__global__ __launch_bounds__(256) void k_gemm10(
    const float* __restrict__ A, const float* __restrict__ W,
    float* __restrict__ C, int M)
{
    __shared__ float Ws[128 * 10];
    int tid = threadIdx.x;
    for (int j = tid; j < 1280; j += 256) Ws[j] = W[j];
    __syncthreads();
    int r = blockIdx.x * 8 + (tid >> 5);
    int lane = tid & 31;
    if (r >= M) return;
    float4 a = *(const float4*)&A[(long long)r * 128 + lane * 4];
    float acc[10];
    #pragma unroll
    for (int c = 0; c < 10; c++) {
        acc[c] = a.x * Ws[(lane * 4 + 0) * 10 + c]
               + a.y * Ws[(lane * 4 + 1) * 10 + c]
               + a.z * Ws[(lane * 4 + 2) * 10 + c]
               + a.w * Ws[(lane * 4 + 3) * 10 + c];
    }
    #pragma unroll
    for (int off = 16; off > 0; off >>= 1)
        #pragma unroll
        for (int c = 0; c < 10; c++)
            acc[c] += __shfl_xor_sync(0xFFFFFFFFu, acc[c], off);
    float v = 0.0f;
    #pragma unroll
    for (int c = 0; c < 10; c++) v = (lane == c) ? acc[c] : v;
    if (lane < 10) C[(long long)r * 10 + lane] = v;
}

__global__ __launch_bounds__(256) void k_gather10(
    const float* __restrict__ hw, const float* __restrict__ bias,
    float* __restrict__ out, int N)
{
    int warp = (blockIdx.x * blockDim.x + threadIdx.x) >> 5;
    int lane = threadIdx.x & 31;
    if (warp >= N) return;
    int beg = g_rowptr[warp];
    int end = g_rowptr[warp + 1];
    float acc = (lane < 10) ? bias[lane] : 0.0f;
    for (int e = beg; e < end; e++) {
        int s = g_src[e];
        float w = g_norm[e];
        float v = (lane < 10) ? hw[(long long)s * 10 + lane] : 0.0f;
        acc = fmaf(w, v, acc);
    }
    if (lane < 10) out[(long long)warp * 10 + lane] = acc;
}

// ---------------- Pooling + log_softmax ----------------
__global__ void k_pool(const int* __restrict__ batch,
                       const float* __restrict__ h10, int N)
{
    int i = blockIdx.x * blockDim.x + threadIdx.x;
    if (i >= N) return;
    int g = batch[i];
    const float* p = &h10[(long long)i * 10];
    #pragma unroll
    for (int c = 0; c < 10; c++) atomicAdd(&g_pool[g * 10 + c], p[c]);
    atomicAdd(&g_cnt[g], 1.0f);
}

__global__ void k_final(float* __restrict__ out) {
    int g = blockIdx.x * blockDim.x + threadIdx.x;
    if (g >= NGRAPH) return;
    float cnt = fmaxf(g_cnt[g], 1.0f);
    float v[10];
    float m = -1e30f;
    #pragma unroll
    for (int c = 0; c < 10; c++) { v[c] = g_pool[g * 10 + c] / cnt; m = fmaxf(m, v[c]); }
    float s = 0.0f;
    #pragma unroll
    for (int c = 0; c < 10; c++) s += __expf(v[c] - m);
    float lse = m + __logf(s);
    #pragma unroll
    for (int c = 0; c < 10; c++) out[g * 10 + c] = v[c] - lse;
}

// ---------------- Launch ----------------
extern "C" void kernel_launch(void* const* d_in, const int* in_sizes, int n_in,
                              void* d_out, int out_size)
{
    const float* x     = (const float*)d_in[0];
    const int*   ei    = (const int*)d_in[1];     // int32 (JAX default int)
    const int*   batch = (const int*)d_in[2];     // int32
    const float* W_in  = (const float*)d_in[3];
    const float* b_in  = (const float*)d_in[4];
    const float* W_h0  = (const float*)d_in[5];
    const float* b_h0  = (const float*)d_in[6];
    const float* W_h1  = (const float*)d_in[7];
    const float* b_h1  = (const float*)d_in[8];
    const float* W_out = (const float*)d_in[9];
    const float* b_out = (const float*)d_in[10];
    float* out = (float*)d_out;

    int N = in_sizes[0] / FDIM;       // 100000
    int E = in_sizes[1] / 2;          // 3200000

    float *hbuf, *hwbuf, *h10a, *h10b;
    cudaGetSymbolAddress((void**)&hbuf,  g_h);
    cudaGetSymbolAddress((void**)&hwbuf, g_hw);
    cudaGetSymbolAddress((void**)&h10a,  g_h10a);
    cudaGetSymbolAddress((void**)&h10b,  g_h10b);

    int tb = 256;
    int gbN = (N + tb - 1) / tb;
    int gbE = (E + tb - 1) / tb;
    int nb  = (N + 1023) / 1024;

    // Graph preprocessing (CSR by dst, self-loops in slot 0)
    k_init<<<gbN, tb>>>(N);
    k_count<<<gbE, tb>>>(ei, E);
    k_dinv<<<gbN, tb>>>(N);
    k_scan_block<<<nb, 1024>>>(N);
    k_scan_sums<<<1, 32>>>(nb, N);
    k_scan_add<<<gbN, tb>>>(N);
    k_selfloop<<<gbN, tb>>>(N);
    k_fill<<<gbE, tb>>>(ei, E);

    int gemmBlocks   = (N + 63) / 64;
    int gatherBlocks = (N + 7) / 8;    // 8 warps per 256-thread block

    // Layer 1: x @ W_in -> gather -> relu
    k_gemm128<<<gemmBlocks, 256>>>(x, W_in, hwbuf, N);
    k_gather128<<<gatherBlocks, 256>>>(hwbuf, b_in, hbuf, N, 1);
    // Layer 2
    k_gemm128<<<gemmBlocks, 256>>>(hbuf, W_h0, hwbuf, N);
    k_gather128<<<gatherBlocks, 256>>>(hwbuf, b_h0, hbuf, N, 1);
    // Layer 3
    k_gemm128<<<gemmBlocks, 256>>>(hbuf, W_h1, hwbuf, N);
    k_gather128<<<gatherBlocks, 256>>>(hwbuf, b_h1, hbuf, N, 1);
    // Output layer (C=10, no relu)
    k_gemm10<<<(N + 7) / 8, 256>>>(hbuf, W_out, h10a, N);
    k_gather10<<<gatherBlocks, 256>>>(h10a, b_out, h10b, N);

    // Mean pool + log_softmax
    k_pool<<<gbN, tb>>>(batch, h10b, N);
    k_final<<<(NGRAPH + 255) / 256, 256>>>(out);
}

// round 6
// speedup vs baseline: 1.0948x; 1.0948x over previous
#include <cuda_runtime.h>
#include <cuda_fp16.h>

// ---------------- Problem constants ----------------
#define NMAX   100000
#define EMAX   3200000
#define ETOT   (EMAX + NMAX)   // edges + self loops
#define FDIM   128
#define CDIM   10
#define NGRAPH 512

// ---------------- Device scratch (static, allocation-free) ----------------
__device__ float  g_h   [NMAX * FDIM];   // aggregated features (layer output, fp32)
__device__ __half g_hw16[NMAX * FDIM];   // GEMM output in fp16 (gather input)
__device__ float  g_h10a[NMAX * CDIM];   // last-layer GEMM output
__device__ float  g_h10b[NMAX * CDIM];   // last-layer aggregated
__device__ int2   g_edge[ETOT];          // packed {src, bits(norm)}
__device__ int    g_rowptr[NMAX + 1];
__device__ int    g_cursor[NMAX];
__device__ int    g_deg [NMAX];
__device__ float  g_dinv[NMAX];
__device__ int    g_bsums[256];
__device__ float  g_pool[NGRAPH * CDIM];
__device__ float  g_cnt [NGRAPH];

// ---------------- Graph preprocessing ----------------

__global__ void k_init(int N) {
    int i = blockIdx.x * blockDim.x + threadIdx.x;
    if (i < N) g_deg[i] = 1;                    // self loop contributes 1
    if (i < NGRAPH * CDIM) g_pool[i] = 0.0f;
    if (i < NGRAPH) g_cnt[i] = 0.0f;
}

// edge_index / batch are INT32 (JAX default int without x64 mode).
__global__ void k_count(const int* __restrict__ ei, int E) {
    int e = blockIdx.x * blockDim.x + threadIdx.x;
    if (e >= E) return;
    atomicAdd(&g_deg[ei[E + e]], 1);
}

__global__ void k_dinv(int N) {
    int i = blockIdx.x * blockDim.x + threadIdx.x;
    if (i >= N) return;
    g_dinv[i] = rsqrtf((float)g_deg[i]);
}

// Per-block exclusive scan of g_deg into g_rowptr; block sums into g_bsums.
__global__ void k_scan_block(int N) {
    __shared__ int sh[1024];
    int tid = threadIdx.x;
    int i = blockIdx.x * 1024 + tid;
    int v = (i < N) ? g_deg[i] : 0;
    sh[tid] = v;
    __syncthreads();
    for (int off = 1; off < 1024; off <<= 1) {
        int t = (tid >= off) ? sh[tid - off] : 0;
        __syncthreads();
        sh[tid] += t;
        __syncthreads();
    }
    if (i < N) g_rowptr[i] = sh[tid] - v;       // exclusive within block
    if (tid == 1023) g_bsums[blockIdx.x] = sh[1023];
}

__global__ void k_scan_sums(int nb, int N) {
    if (threadIdx.x == 0 && blockIdx.x == 0) {
        int run = 0;
        for (int b = 0; b < nb; b++) { int t = g_bsums[b]; g_bsums[b] = run; run += t; }
        g_rowptr[N] = run;
    }
}

__global__ void k_scan_add(int N) {
    int i = blockIdx.x * blockDim.x + threadIdx.x;
    if (i >= N) return;
    g_rowptr[i] += g_bsums[i >> 10];
}

// Self-loop goes in slot 0 of each node's segment; cursor starts after it.
__global__ void k_selfloop(int N) {
    int i = blockIdx.x * blockDim.x + threadIdx.x;
    if (i >= N) return;
    int p = g_rowptr[i];
    float di = g_dinv[i];
    g_edge[p] = make_int2(i, __float_as_int(di * di));
    g_cursor[i] = p + 1;
}

__global__ void k_fill(const int* __restrict__ ei, int E) {
    int e = blockIdx.x * blockDim.x + threadIdx.x;
    if (e >= E) return;
    int s = ei[e];
    int d = ei[E + e];
    int p = atomicAdd(&g_cursor[d], 1);
    g_edge[p] = make_int2(s, __float_as_int(g_dinv[s] * g_dinv[d]));
}

// ---------------- SGEMM: C[M,128](fp16) = A[M,128](fp32) @ W[128,128] --------
// BM=64, BN=128, BK=16, 256 threads, 4x8 thread tile; fp16 epilogue.
__global__ __launch_bounds__(256) void k_gemm128(
    const float* __restrict__ A, const float* __restrict__ W,
    __half* __restrict__ C, int M)
{
    __shared__ float As[16][65];    // padded (transposed) A tile
    __shared__ float Ws[16][128];
    int tid = threadIdx.x;
    int row0 = blockIdx.x * 64;
    int trow = (tid / 16) * 4;
    int tcol = (tid % 16) * 8;
    int arow = tid / 4;
    int ak   = (tid % 4) * 4;
    int wrow = tid / 32;
    int wcol = (tid % 32) * 4;

    float acc[4][8];
    #pragma unroll
    for (int i = 0; i < 4; i++)
        #pragma unroll
        for (int j = 0; j < 8; j++) acc[i][j] = 0.0f;

    for (int k0 = 0; k0 < 128; k0 += 16) {
        int gr = row0 + arow;
        float4 av = (gr < M) ? *(const float4*)&A[(long long)gr * 128 + k0 + ak]
                             : make_float4(0.f, 0.f, 0.f, 0.f);
        As[ak + 0][arow] = av.x; As[ak + 1][arow] = av.y;
        As[ak + 2][arow] = av.z; As[ak + 3][arow] = av.w;
        *(float4*)&Ws[wrow][wcol]     = *(const float4*)&W[(k0 + wrow) * 128 + wcol];
        *(float4*)&Ws[wrow + 8][wcol] = *(const float4*)&W[(k0 + wrow + 8) * 128 + wcol];
        __syncthreads();
        #pragma unroll
        for (int k = 0; k < 16; k++) {
            float a[4];
            #pragma unroll
            for (int i = 0; i < 4; i++) a[i] = As[k][trow + i];
            float b[8];
            #pragma unroll
            for (int j = 0; j < 8; j++) b[j] = Ws[k][tcol + j];
            #pragma unroll
            for (int i = 0; i < 4; i++)
                #pragma unroll
                for (int j = 0; j < 8; j++) acc[i][j] = fmaf(a[i], b[j], acc[i][j]);
        }
        __syncthreads();
    }
    #pragma unroll
    for (int i = 0; i < 4; i++) {
        int row = row0 + trow + i;
        if (row < M) {
            __half2 h0 = __floats2half2_rn(acc[i][0], acc[i][1]);
            __half2 h1 = __floats2half2_rn(acc[i][2], acc[i][3]);
            __half2 h2 = __floats2half2_rn(acc[i][4], acc[i][5]);
            __half2 h3 = __floats2half2_rn(acc[i][6], acc[i][7]);
            uint4 v;
            v.x = *(unsigned*)&h0; v.y = *(unsigned*)&h1;
            v.z = *(unsigned*)&h2; v.w = *(unsigned*)&h3;
            *(uint4*)&C[(long long)row * 128 + tcol] = v;   // 16B store (8 halves)
        }
    }
}

// ---------------- Edge aggregation (pull, warp per node, D=128, fp16 in) -----
__device__ __forceinline__ float4 ld_half4(const __half* base, long long s, int lane) {
    uint2 raw = *(const uint2*)&base[s * 128 + lane * 4];
    __half2 a0 = *(__half2*)&raw.x;
    __half2 a1 = *(__half2*)&raw.y;
    float2 f0 = __half22float2(a0);
    float2 f1 = __half22float2(a1);
    return make_float4(f0.x, f0.y, f1.x, f1.y);
}

__global__ __launch_bounds__(256) void k_gather128(
    const __half* __restrict__ hw, const float* __restrict__ bias,
    float* __restrict__ out, int N, int do_relu)
{
    int warp = (blockIdx.x * blockDim.x + threadIdx.x) >> 5;
    int lane = threadIdx.x & 31;
    if (warp >= N) return;
    int beg = g_rowptr[warp];
    int end = g_rowptr[warp + 1];
    float4 acc = *(const float4*)&bias[lane * 4];
    int e = beg;
    for (; e + 4 <= end; e += 4) {
        int2 e0 = g_edge[e],     e1 = g_edge[e + 1];
        int2 e2 = g_edge[e + 2], e3 = g_edge[e + 3];
        float w0 = __int_as_float(e0.y), w1 = __int_as_float(e1.y);
        float w2 = __int_as_float(e2.y), w3 = __int_as_float(e3.y);
        float4 v0 = ld_half4(hw, e0.x, lane);
        float4 v1 = ld_half4(hw, e1.x, lane);
        float4 v2 = ld_half4(hw, e2.x, lane);
        float4 v3 = ld_half4(hw, e3.x, lane);
        acc.x = fmaf(w0, v0.x, acc.x); acc.y = fmaf(w0, v0.y, acc.y);
        acc.z = fmaf(w0, v0.z, acc.z); acc.w = fmaf(w0, v0.w, acc.w);
        acc.x = fmaf(w1, v1.x, acc.x); acc.y = fmaf(w1, v1.y, acc.y);
        acc.z = fmaf(w1, v1.z, acc.z); acc.w = fmaf(w1, v1.w, acc.w);
        acc.x = fmaf(w2, v2.x, acc.x); acc.y = fmaf(w2, v2.y, acc.y);
        acc.z = fmaf(w2, v2.z, acc.z); acc.w = fmaf(w2, v2.w, acc.w);
        acc.x = fmaf(w3, v3.x, acc.x); acc.y = fmaf(w3, v3.y, acc.y);
        acc.z = fmaf(w3, v3.z, acc.z); acc.w = fmaf(w3, v3.w, acc.w);
    }
    for (; e < end; e++) {
        int2 ed = g_edge[e];
        float w = __int_as_float(ed.y);
        float4 v = ld_half4(hw, ed.x, lane);
        acc.x = fmaf(w, v.x, acc.x); acc.y = fmaf(w, v.y, acc.y);
        acc.z = fmaf(w, v.z, acc.z); acc.w = fmaf(w, v.w, acc.w);
    }
    if (do_relu) {
        acc.x = fmaxf(acc.x, 0.f); acc.y = fmaxf(acc.y, 0.f);
        acc.z = fmaxf(acc.z, 0.f); acc.w = fmaxf(acc.w, 0.f);
    }
    *(float4*)&out[(long long)warp * 128 + lane * 4] = acc;
}

// ---------------- Last layer: C[M,10] = A[M,128] @ W[128,10] (warp per row) ----
__global__ __launch_bounds__(256) void k_gemm10(
    const float* __restrict__ A, const float* __restrict__ W,
    float* __restrict__ C, int M)
{
    __shared__ float Ws[128 * 10];
    int tid = threadIdx.x;
    for (int j = tid; j < 1280; j += 256) Ws[j] = W[j];
    __syncthreads();
    int r = blockIdx.x * 8 + (tid >> 5);
    int lane = tid & 31;
    if (r >= M) return;
    float4 a = *(const float4*)&A[(long long)r * 128 + lane * 4];
    float acc[10];
    #pragma unroll
    for (int c = 0; c < 10; c++) {
        acc[c] = a.x * Ws[(lane * 4 + 0) * 10 + c]
               + a.y * Ws[(lane * 4 + 1) * 10 + c]
               + a.z * Ws[(lane * 4 + 2) * 10 + c]
               + a.w * Ws[(lane * 4 + 3) * 10 + c];
    }
    #pragma unroll
    for (int off = 16; off > 0; off >>= 1)
        #pragma unroll
        for (int c = 0; c < 10; c++)
            acc[c] += __shfl_xor_sync(0xFFFFFFFFu, acc[c], off);
    float v = 0.0f;
    #pragma unroll
    for (int c = 0; c < 10; c++) v = (lane == c) ? acc[c] : v;
    if (lane < 10) C[(long long)r * 10 + lane] = v;
}

__global__ __launch_bounds__(256) void k_gather10(
    const float* __restrict__ hw, const float* __restrict__ bias,
    float* __restrict__ out, int N)
{
    int warp = (blockIdx.x * blockDim.x + threadIdx.x) >> 5;
    int lane = threadIdx.x & 31;
    if (warp >= N) return;
    int beg = g_rowptr[warp];
    int end = g_rowptr[warp + 1];
    float acc = (lane < 10) ? bias[lane] : 0.0f;
    for (int e = beg; e < end; e++) {
        int2 ed = g_edge[e];
        float w = __int_as_float(ed.y);
        float v = (lane < 10) ? hw[(long long)ed.x * 10 + lane] : 0.0f;
        acc = fmaf(w, v, acc);
    }
    if (lane < 10) out[(long long)warp * 10 + lane] = acc;
}

// ---------------- Pooling + log_softmax ----------------
__global__ void k_pool(const int* __restrict__ batch,
                       const float* __restrict__ h10, int N)
{
    int i = blockIdx.x * blockDim.x + threadIdx.x;
    if (i >= N) return;
    int g = batch[i];
    const float* p = &h10[(long long)i * 10];
    #pragma unroll
    for (int c = 0; c < 10; c++) atomicAdd(&g_pool[g * 10 + c], p[c]);
    atomicAdd(&g_cnt[g], 1.0f);
}

__global__ void k_final(float* __restrict__ out) {
    int g = blockIdx.x * blockDim.x + threadIdx.x;
    if (g >= NGRAPH) return;
    float cnt = fmaxf(g_cnt[g], 1.0f);
    float v[10];
    float m = -1e30f;
    #pragma unroll
    for (int c = 0; c < 10; c++) { v[c] = g_pool[g * 10 + c] / cnt; m = fmaxf(m, v[c]); }
    float s = 0.0f;
    #pragma unroll
    for (int c = 0; c < 10; c++) s += __expf(v[c] - m);
    float lse = m + __logf(s);
    #pragma unroll
    for (int c = 0; c < 10; c++) out[g * 10 + c] = v[c] - lse;
}

// ---------------- Launch ----------------
extern "C" void kernel_launch(void* const* d_in, const int* in_sizes, int n_in,
                              void* d_out, int out_size)
{
    const float* x     = (const float*)d_in[0];
    const int*   ei    = (const int*)d_in[1];     // int32
    const int*   batch = (const int*)d_in[2];     // int32
    const float* W_in  = (const float*)d_in[3];
    const float* b_in  = (const float*)d_in[4];
    const float* W_h0  = (const float*)d_in[5];
    const float* b_h0  = (const float*)d_in[6];
    const float* W_h1  = (const float*)d_in[7];
    const float* b_h1  = (const float*)d_in[8];
    const float* W_out = (const float*)d_in[9];
    const float* b_out = (const float*)d_in[10];
    float* out = (float*)d_out;

    int N = in_sizes[0] / FDIM;       // 100000
    int E = in_sizes[1] / 2;          // 3200000

    float *hbuf, *h10a, *h10b;
    __half *hw16;
    cudaGetSymbolAddress((void**)&hbuf,  g_h);
    cudaGetSymbolAddress((void**)&hw16,  g_hw16);
    cudaGetSymbolAddress((void**)&h10a,  g_h10a);
    cudaGetSymbolAddress((void**)&h10b,  g_h10b);

    int tb = 256;
    int gbN = (N + tb - 1) / tb;
    int gbE = (E + tb - 1) / tb;
    int nb  = (N + 1023) / 1024;

    // Graph preprocessing (CSR by dst, self-loops in slot 0)
    k_init<<<gbN, tb>>>(N);
    k_count<<<gbE, tb>>>(ei, E);
    k_dinv<<<gbN, tb>>>(N);
    k_scan_block<<<nb, 1024>>>(N);
    k_scan_sums<<<1, 32>>>(nb, N);
    k_scan_add<<<gbN, tb>>>(N);
    k_selfloop<<<gbN, tb>>>(N);
    k_fill<<<gbE, tb>>>(ei, E);

    int gemmBlocks   = (N + 63) / 64;
    int gatherBlocks = (N + 7) / 8;    // 8 warps per 256-thread block

    // Layer 1: x @ W_in -> gather -> relu
    k_gemm128<<<gemmBlocks, 256>>>(x, W_in, hw16, N);
    k_gather128<<<gatherBlocks, 256>>>(hw16, b_in, hbuf, N, 1);
    // Layer 2
    k_gemm128<<<gemmBlocks, 256>>>(hbuf, W_h0, hw16, N);
    k_gather128<<<gatherBlocks, 256>>>(hw16, b_h0, hbuf, N, 1);
    // Layer 3
    k_gemm128<<<gemmBlocks, 256>>>(hbuf, W_h1, hw16, N);
    k_gather128<<<gatherBlocks, 256>>>(hw16, b_h1, hbuf, N, 1);
    // Output layer (C=10, no relu)
    k_gemm10<<<(N + 7) / 8, 256>>>(hbuf, W_out, h10a, N);
    k_gather10<<<gatherBlocks, 256>>>(h10a, b_out, h10b, N);

    // Mean pool + log_softmax
    k_pool<<<gbN, tb>>>(batch, h10b, N);
    k_final<<<(NGRAPH + 255) / 256, 256>>>(out);
}

// round 7
// speedup vs baseline: 1.4958x; 1.3662x over previous
#include <cuda_runtime.h>
#include <cuda_fp16.h>

// ---------------- Problem constants ----------------
#define NMAX   100000
#define EMAX   3200000
#define ETOT   (EMAX + NMAX)   // edges + self loops
#define FDIM   128
#define CDIM   10
#define NGRAPH 512

// ---------------- Device scratch (static, allocation-free) ----------------
__device__ __half g_f16a[NMAX * FDIM];   // GEMM input  (gather output / cvt(x))
__device__ __half g_f16b[NMAX * FDIM];   // GEMM output (gather input)
__device__ __half g_Wt  [3 * FDIM * FDIM]; // fp16 transposed weights Wt[n][k]
__device__ float  g_h10a[NMAX * CDIM];   // last-layer GEMM output
__device__ float  g_h10b[NMAX * CDIM];   // last-layer aggregated
__device__ int2   g_edge[ETOT];          // packed {src, bits(norm)}
__device__ int    g_rowptr[NMAX + 1];
__device__ int    g_cursor[NMAX];
__device__ int    g_deg [NMAX];
__device__ float  g_dinv[NMAX];
__device__ int    g_bsums[256];
__device__ float  g_pool[NGRAPH * CDIM];
__device__ float  g_cnt [NGRAPH];

// ---------------- Graph preprocessing ----------------

__global__ void k_init(int N) {
    int i = blockIdx.x * blockDim.x + threadIdx.x;
    if (i < N) g_deg[i] = 1;                    // self loop contributes 1
    if (i < NGRAPH * CDIM) g_pool[i] = 0.0f;
    if (i < NGRAPH) g_cnt[i] = 0.0f;
}

__global__ void k_count(const int* __restrict__ ei, int E) {
    int e = blockIdx.x * blockDim.x + threadIdx.x;
    if (e >= E) return;
    atomicAdd(&g_deg[ei[E + e]], 1);
}

__global__ void k_dinv(int N) {
    int i = blockIdx.x * blockDim.x + threadIdx.x;
    if (i >= N) return;
    g_dinv[i] = rsqrtf((float)g_deg[i]);
}

__global__ void k_scan_block(int N) {
    __shared__ int sh[1024];
    int tid = threadIdx.x;
    int i = blockIdx.x * 1024 + tid;
    int v = (i < N) ? g_deg[i] : 0;
    sh[tid] = v;
    __syncthreads();
    for (int off = 1; off < 1024; off <<= 1) {
        int t = (tid >= off) ? sh[tid - off] : 0;
        __syncthreads();
        sh[tid] += t;
        __syncthreads();
    }
    if (i < N) g_rowptr[i] = sh[tid] - v;
    if (tid == 1023) g_bsums[blockIdx.x] = sh[1023];
}

__global__ void k_scan_sums(int nb, int N) {
    if (threadIdx.x == 0 && blockIdx.x == 0) {
        int run = 0;
        for (int b = 0; b < nb; b++) { int t = g_bsums[b]; g_bsums[b] = run; run += t; }
        g_rowptr[N] = run;
    }
}

__global__ void k_scan_add(int N) {
    int i = blockIdx.x * blockDim.x + threadIdx.x;
    if (i >= N) return;
    g_rowptr[i] += g_bsums[i >> 10];
}

__global__ void k_selfloop(int N) {
    int i = blockIdx.x * blockDim.x + threadIdx.x;
    if (i >= N) return;
    int p = g_rowptr[i];
    float di = g_dinv[i];
    g_edge[p] = make_int2(i, __float_as_int(di * di));
    g_cursor[i] = p + 1;
}

__global__ void k_fill(const int* __restrict__ ei, int E) {
    int e = blockIdx.x * blockDim.x + threadIdx.x;
    if (e >= E) return;
    int s = ei[e];
    int d = ei[E + e];
    int p = atomicAdd(&g_cursor[d], 1);
    g_edge[p] = make_int2(s, __float_as_int(g_dinv[s] * g_dinv[d]));
}

// ---------------- Weight prep: W fp32 [k][n] -> Wt fp16 [n][k] ----------------
__global__ void k_prepW(const float* __restrict__ W, __half* __restrict__ Wt) {
    int idx = blockIdx.x * blockDim.x + threadIdx.x;   // 16384
    if (idx >= FDIM * FDIM) return;
    int n = idx >> 7, k = idx & 127;
    Wt[n * FDIM + k] = __float2half(W[k * FDIM + n]);
}

// ---------------- x fp32 -> fp16 ----------------
__global__ void k_cvt(const float* __restrict__ x, __half* __restrict__ o, int total4) {
    int i = blockIdx.x * blockDim.x + threadIdx.x;
    if (i >= total4) return;
    float4 v = *(const float4*)&x[i * 4];
    __half2 h0 = __floats2half2_rn(v.x, v.y);
    __half2 h1 = __floats2half2_rn(v.z, v.w);
    uint2 u; u.x = *(unsigned*)&h0; u.y = *(unsigned*)&h1;
    *(uint2*)&o[i * 4] = u;
}

// ---------------- Tensor-core GEMM: C[M,128] = A[M,128] @ W, fp16 in, fp16 out
__device__ __forceinline__ void mma16816(float c[4],
    unsigned a0, unsigned a1, unsigned a2, unsigned a3, unsigned b0, unsigned b1)
{
    asm volatile(
        "mma.sync.aligned.m16n8k16.row.col.f32.f16.f16.f32 "
        "{%0,%1,%2,%3}, {%4,%5,%6,%7}, {%8,%9}, {%0,%1,%2,%3};"
        : "+f"(c[0]), "+f"(c[1]), "+f"(c[2]), "+f"(c[3])
        : "r"(a0), "r"(a1), "r"(a2), "r"(a3), "r"(b0), "r"(b1));
}

__global__ __launch_bounds__(256, 1) void k_gemmTC(
    const __half* __restrict__ A, const __half* __restrict__ Wt,
    __half* __restrict__ C, int M)
{
    __shared__ __half As[128][136];            // 136-half pad -> conflict-free frags
    int tid = threadIdx.x;
    int wid = tid >> 5, lane = tid & 31;
    int group = lane >> 2, t = lane & 3;
    int row0 = blockIdx.x * 128;

    // Load A tile (fp16): 8 iterations of 16B per thread
    {
        int r = tid >> 4;                      // 0..15
        int c = (tid & 15) * 8;                // 0..120
        #pragma unroll
        for (int rr = 0; rr < 128; rr += 16) {
            int gr = row0 + rr + r;
            uint4 v = make_uint4(0u, 0u, 0u, 0u);
            if (gr < M) v = *(const uint4*)&A[(long long)gr * FDIM + c];
            *(uint4*)&As[rr + r][c] = v;
        }
    }
    __syncthreads();

    int warp_m = (wid & 3) * 32;               // 0,32,64,96
    int warp_n = (wid >> 2) * 64;              // 0,64

    float acc[2][8][4];
    #pragma unroll
    for (int mt = 0; mt < 2; mt++)
        #pragma unroll
        for (int nt = 0; nt < 8; nt++)
            #pragma unroll
            for (int q = 0; q < 4; q++) acc[mt][nt][q] = 0.0f;

    #pragma unroll
    for (int ks = 0; ks < 8; ks++) {
        int k0 = ks * 16;
        unsigned b[8][2];
        #pragma unroll
        for (int nt = 0; nt < 8; nt++) {
            const __half* wp = &Wt[(warp_n + nt * 8 + group) * FDIM + k0 + t * 2];
            b[nt][0] = *(const unsigned*)wp;        // k0+t2, k0+t2+1
            b[nt][1] = *(const unsigned*)(wp + 8);  // +8, +9
        }
        #pragma unroll
        for (int mt = 0; mt < 2; mt++) {
            int r = warp_m + mt * 16 + group;
            unsigned a0 = *(const unsigned*)&As[r][k0 + t * 2];
            unsigned a1 = *(const unsigned*)&As[r + 8][k0 + t * 2];
            unsigned a2 = *(const unsigned*)&As[r][k0 + t * 2 + 8];
            unsigned a3 = *(const unsigned*)&As[r + 8][k0 + t * 2 + 8];
            #pragma unroll
            for (int nt = 0; nt < 8; nt++)
                mma16816(acc[mt][nt], a0, a1, a2, a3, b[nt][0], b[nt][1]);
        }
    }

    // Epilogue: fp16 store
    #pragma unroll
    for (int mt = 0; mt < 2; mt++) {
        #pragma unroll
        for (int nt = 0; nt < 8; nt++) {
            int r  = row0 + warp_m + mt * 16 + group;
            int cc = warp_n + nt * 8 + t * 2;
            if (r < M) {
                __half2 h = __floats2half2_rn(acc[mt][nt][0], acc[mt][nt][1]);
                *(unsigned*)&C[(long long)r * FDIM + cc] = *(unsigned*)&h;
            }
            if (r + 8 < M) {
                __half2 h = __floats2half2_rn(acc[mt][nt][2], acc[mt][nt][3]);
                *(unsigned*)&C[(long long)(r + 8) * FDIM + cc] = *(unsigned*)&h;
            }
        }
    }
}

// ---------------- Edge aggregation (pull, warp per node, fp16 in/out) --------
__device__ __forceinline__ float4 ld_half4(const __half* base, long long s, int lane) {
    uint2 raw = *(const uint2*)&base[s * FDIM + lane * 4];
    __half2 a0 = *(__half2*)&raw.x;
    __half2 a1 = *(__half2*)&raw.y;
    float2 f0 = __half22float2(a0);
    float2 f1 = __half22float2(a1);
    return make_float4(f0.x, f0.y, f1.x, f1.y);
}

__global__ __launch_bounds__(256) void k_gather128(
    const __half* __restrict__ hw, const float* __restrict__ bias,
    __half* __restrict__ out, int N, int do_relu)
{
    int warp = (blockIdx.x * blockDim.x + threadIdx.x) >> 5;
    int lane = threadIdx.x & 31;
    if (warp >= N) return;
    int beg = g_rowptr[warp];
    int end = g_rowptr[warp + 1];
    float4 acc = *(const float4*)&bias[lane * 4];
    int e = beg;
    for (; e + 4 <= end; e += 4) {
        int2 e0 = g_edge[e],     e1 = g_edge[e + 1];
        int2 e2 = g_edge[e + 2], e3 = g_edge[e + 3];
        float w0 = __int_as_float(e0.y), w1 = __int_as_float(e1.y);
        float w2 = __int_as_float(e2.y), w3 = __int_as_float(e3.y);
        float4 v0 = ld_half4(hw, e0.x, lane);
        float4 v1 = ld_half4(hw, e1.x, lane);
        float4 v2 = ld_half4(hw, e2.x, lane);
        float4 v3 = ld_half4(hw, e3.x, lane);
        acc.x = fmaf(w0, v0.x, acc.x); acc.y = fmaf(w0, v0.y, acc.y);
        acc.z = fmaf(w0, v0.z, acc.z); acc.w = fmaf(w0, v0.w, acc.w);
        acc.x = fmaf(w1, v1.x, acc.x); acc.y = fmaf(w1, v1.y, acc.y);
        acc.z = fmaf(w1, v1.z, acc.z); acc.w = fmaf(w1, v1.w, acc.w);
        acc.x = fmaf(w2, v2.x, acc.x); acc.y = fmaf(w2, v2.y, acc.y);
        acc.z = fmaf(w2, v2.z, acc.z); acc.w = fmaf(w2, v2.w, acc.w);
        acc.x = fmaf(w3, v3.x, acc.x); acc.y = fmaf(w3, v3.y, acc.y);
        acc.z = fmaf(w3, v3.z, acc.z); acc.w = fmaf(w3, v3.w, acc.w);
    }
    for (; e < end; e++) {
        int2 ed = g_edge[e];
        float w = __int_as_float(ed.y);
        float4 v = ld_half4(hw, ed.x, lane);
        acc.x = fmaf(w, v.x, acc.x); acc.y = fmaf(w, v.y, acc.y);
        acc.z = fmaf(w, v.z, acc.z); acc.w = fmaf(w, v.w, acc.w);
    }
    if (do_relu) {
        acc.x = fmaxf(acc.x, 0.f); acc.y = fmaxf(acc.y, 0.f);
        acc.z = fmaxf(acc.z, 0.f); acc.w = fmaxf(acc.w, 0.f);
    }
    __half2 h0 = __floats2half2_rn(acc.x, acc.y);
    __half2 h1 = __floats2half2_rn(acc.z, acc.w);
    uint2 u; u.x = *(unsigned*)&h0; u.y = *(unsigned*)&h1;
    *(uint2*)&out[(long long)warp * FDIM + lane * 4] = u;
}

// ---------------- Last layer: C[M,10] = A[M,128](fp16) @ W[128,10] -----------
__global__ __launch_bounds__(256) void k_gemm10(
    const __half* __restrict__ A, const float* __restrict__ W,
    float* __restrict__ C, int M)
{
    __shared__ float Ws[128 * 10];
    int tid = threadIdx.x;
    for (int j = tid; j < 1280; j += 256) Ws[j] = W[j];
    __syncthreads();
    int r = blockIdx.x * 8 + (tid >> 5);
    int lane = tid & 31;
    if (r >= M) return;
    float4 a = ld_half4(A, r, lane);
    float acc[10];
    #pragma unroll
    for (int c = 0; c < 10; c++) {
        acc[c] = a.x * Ws[(lane * 4 + 0) * 10 + c]
               + a.y * Ws[(lane * 4 + 1) * 10 + c]
               + a.z * Ws[(lane * 4 + 2) * 10 + c]
               + a.w * Ws[(lane * 4 + 3) * 10 + c];
    }
    #pragma unroll
    for (int off = 16; off > 0; off >>= 1)
        #pragma unroll
        for (int c = 0; c < 10; c++)
            acc[c] += __shfl_xor_sync(0xFFFFFFFFu, acc[c], off);
    float v = 0.0f;
    #pragma unroll
    for (int c = 0; c < 10; c++) v = (lane == c) ? acc[c] : v;
    if (lane < 10) C[(long long)r * 10 + lane] = v;
}

__global__ __launch_bounds__(256) void k_gather10(
    const float* __restrict__ hw, const float* __restrict__ bias,
    float* __restrict__ out, int N)
{
    int warp = (blockIdx.x * blockDim.x + threadIdx.x) >> 5;
    int lane = threadIdx.x & 31;
    if (warp >= N) return;
    int beg = g_rowptr[warp];
    int end = g_rowptr[warp + 1];
    float acc = (lane < 10) ? bias[lane] : 0.0f;
    for (int e = beg; e < end; e++) {
        int2 ed = g_edge[e];
        float w = __int_as_float(ed.y);
        float v = (lane < 10) ? hw[(long long)ed.x * 10 + lane] : 0.0f;
        acc = fmaf(w, v, acc);
    }
    if (lane < 10) out[(long long)warp * 10 + lane] = acc;
}

// ---------------- Pooling + log_softmax ----------------
__global__ void k_pool(const int* __restrict__ batch,
                       const float* __restrict__ h10, int N)
{
    int i = blockIdx.x * blockDim.x + threadIdx.x;
    if (i >= N) return;
    int g = batch[i];
    const float* p = &h10[(long long)i * 10];
    #pragma unroll
    for (int c = 0; c < 10; c++) atomicAdd(&g_pool[g * 10 + c], p[c]);
    atomicAdd(&g_cnt[g], 1.0f);
}

__global__ void k_final(float* __restrict__ out) {
    int g = blockIdx.x * blockDim.x + threadIdx.x;
    if (g >= NGRAPH) return;
    float cnt = fmaxf(g_cnt[g], 1.0f);
    float v[10];
    float m = -1e30f;
    #pragma unroll
    for (int c = 0; c < 10; c++) { v[c] = g_pool[g * 10 + c] / cnt; m = fmaxf(m, v[c]); }
    float s = 0.0f;
    #pragma unroll
    for (int c = 0; c < 10; c++) s += __expf(v[c] - m);
    float lse = m + __logf(s);
    #pragma unroll
    for (int c = 0; c < 10; c++) out[g * 10 + c] = v[c] - lse;
}

// ---------------- Launch ----------------
extern "C" void kernel_launch(void* const* d_in, const int* in_sizes, int n_in,
                              void* d_out, int out_size)
{
    const float* x     = (const float*)d_in[0];
    const int*   ei    = (const int*)d_in[1];     // int32
    const int*   batch = (const int*)d_in[2];     // int32
    const float* W_in  = (const float*)d_in[3];
    const float* b_in  = (const float*)d_in[4];
    const float* W_h0  = (const float*)d_in[5];
    const float* b_h0  = (const float*)d_in[6];
    const float* W_h1  = (const float*)d_in[7];
    const float* b_h1  = (const float*)d_in[8];
    const float* W_out = (const float*)d_in[9];
    const float* b_out = (const float*)d_in[10];
    float* out = (float*)d_out;

    int N = in_sizes[0] / FDIM;       // 100000
    int E = in_sizes[1] / 2;          // 3200000

    __half *f16a, *f16b, *Wt;
    float *h10a, *h10b;
    cudaGetSymbolAddress((void**)&f16a, g_f16a);
    cudaGetSymbolAddress((void**)&f16b, g_f16b);
    cudaGetSymbolAddress((void**)&Wt,   g_Wt);
    cudaGetSymbolAddress((void**)&h10a, g_h10a);
    cudaGetSymbolAddress((void**)&h10b, g_h10b);

    int tb = 256;
    int gbN = (N + tb - 1) / tb;
    int gbE = (E + tb - 1) / tb;
    int nb  = (N + 1023) / 1024;

    // Graph preprocessing (CSR by dst, self-loops in slot 0)
    k_init<<<gbN, tb>>>(N);
    k_count<<<gbE, tb>>>(ei, E);
    k_dinv<<<gbN, tb>>>(N);
    k_scan_block<<<nb, 1024>>>(N);
    k_scan_sums<<<1, 32>>>(nb, N);
    k_scan_add<<<gbN, tb>>>(N);
    k_selfloop<<<gbN, tb>>>(N);
    k_fill<<<gbE, tb>>>(ei, E);

    // Weight conversion (tiny) + x -> fp16
    k_prepW<<<64, 256>>>(W_in, Wt);
    k_prepW<<<64, 256>>>(W_h0, Wt + FDIM * FDIM);
    k_prepW<<<64, 256>>>(W_h1, Wt + 2 * FDIM * FDIM);
    int total4 = N * FDIM / 4;
    k_cvt<<<(total4 + 255) / 256, 256>>>(x, f16a, total4);

    int gemmBlocks   = (N + 127) / 128;
    int gatherBlocks = (N + 7) / 8;    // 8 warps per 256-thread block

    // Layer 1
    k_gemmTC<<<gemmBlocks, 256>>>(f16a, Wt, f16b, N);
    k_gather128<<<gatherBlocks, 256>>>(f16b, b_in, f16a, N, 1);
    // Layer 2
    k_gemmTC<<<gemmBlocks, 256>>>(f16a, Wt + FDIM * FDIM, f16b, N);
    k_gather128<<<gatherBlocks, 256>>>(f16b, b_h0, f16a, N, 1);
    // Layer 3
    k_gemmTC<<<gemmBlocks, 256>>>(f16a, Wt + 2 * FDIM * FDIM, f16b, N);
    k_gather128<<<gatherBlocks, 256>>>(f16b, b_h1, f16a, N, 1);
    // Output layer (C=10, no relu)
    k_gemm10<<<(N + 7) / 8, 256>>>(f16a, W_out, h10a, N);
    k_gather10<<<gatherBlocks, 256>>>(h10a, b_out, h10b, N);

    // Mean pool + log_softmax
    k_pool<<<gbN, tb>>>(batch, h10b, N);
    k_final<<<(NGRAPH + 255) / 256, 256>>>(out);
}

// round 10
// speedup vs baseline: 1.6456x; 1.1002x over previous
#include <cuda_runtime.h>
#include <cuda_fp16.h>

// ---------------- Problem constants ----------------
#define NMAX   100000
#define EMAX   3200000
#define ETOT   (EMAX + NMAX)   // edges + self loops
#define FDIM   128
#define CDIM   10
#define NGRAPH 512

// ---------------- Device scratch (static, allocation-free) ----------------
__device__ __half g_f16a[NMAX * FDIM];     // GEMM input  (gather output / cvt(x))
__device__ __half g_f16b[NMAX * FDIM];     // GEMM output (gather input, dinv-prescaled)
__device__ __half g_Wt  [3 * FDIM * FDIM]; // fp16 transposed weights Wt[n][k]
__device__ float  g_h10a[NMAX * CDIM];     // last-layer GEMM output (dinv-prescaled)
__device__ float  g_h10b[NMAX * CDIM];     // last-layer aggregated
__device__ int    g_srcs[ETOT];            // CSR-by-dst src indices (self loop slot 0)
__device__ int    g_rowptr[NMAX + 1];
__device__ int    g_cursor[NMAX];
__device__ int    g_deg [NMAX];
__device__ float  g_dinv[NMAX];
__device__ int    g_bsums[256];
__device__ float  g_pool[NGRAPH * CDIM];
__device__ float  g_cnt [NGRAPH];

// ---------------- Graph preprocessing ----------------

__global__ void k_init(int N) {
    int i = blockIdx.x * blockDim.x + threadIdx.x;
    if (i < N) g_deg[i] = 1;                    // self loop contributes 1
    if (i < NGRAPH * CDIM) g_pool[i] = 0.0f;
    if (i < NGRAPH) g_cnt[i] = 0.0f;
}

__global__ void k_count(const int* __restrict__ ei, int E) {
    int e = blockIdx.x * blockDim.x + threadIdx.x;
    if (e >= E) return;
    atomicAdd(&g_deg[ei[E + e]], 1);
}

__global__ void k_dinv(int N) {
    int i = blockIdx.x * blockDim.x + threadIdx.x;
    if (i >= N) return;
    g_dinv[i] = rsqrtf((float)g_deg[i]);
}

__global__ void k_scan_block(int N) {
    __shared__ int sh[1024];
    int tid = threadIdx.x;
    int i = blockIdx.x * 1024 + tid;
    int v = (i < N) ? g_deg[i] : 0;
    sh[tid] = v;
    __syncthreads();
    for (int off = 1; off < 1024; off <<= 1) {
        int t = (tid >= off) ? sh[tid - off] : 0;
        __syncthreads();
        sh[tid] += t;
        __syncthreads();
    }
    if (i < N) g_rowptr[i] = sh[tid] - v;
    if (tid == 1023) g_bsums[blockIdx.x] = sh[1023];
}

__global__ void k_scan_sums(int nb, int N) {
    if (threadIdx.x == 0 && blockIdx.x == 0) {
        int run = 0;
        for (int b = 0; b < nb; b++) { int t = g_bsums[b]; g_bsums[b] = run; run += t; }
        g_rowptr[N] = run;
    }
}

__global__ void k_scan_add(int N) {
    int i = blockIdx.x * blockDim.x + threadIdx.x;
    if (i >= N) return;
    g_rowptr[i] += g_bsums[i >> 10];
}

__global__ void k_selfloop(int N) {
    int i = blockIdx.x * blockDim.x + threadIdx.x;
    if (i >= N) return;
    int p = g_rowptr[i];
    g_srcs[p] = i;
    g_cursor[i] = p + 1;
}

__global__ void k_fill(const int* __restrict__ ei, int E) {
    int e = blockIdx.x * blockDim.x + threadIdx.x;
    if (e >= E) return;
    int s = ei[e];
    int d = ei[E + e];
    int p = atomicAdd(&g_cursor[d], 1);
    g_srcs[p] = s;
}

// ---------------- Weight prep: W fp32 [k][n] -> Wt fp16 [n][k] ----------------
__global__ void k_prepW(const float* __restrict__ W, __half* __restrict__ Wt) {
    int idx = blockIdx.x * blockDim.x + threadIdx.x;   // 16384
    if (idx >= FDIM * FDIM) return;
    int n = idx >> 7, k = idx & 127;
    Wt[n * FDIM + k] = __float2half(W[k * FDIM + n]);
}

// ---------------- x fp32 -> fp16 ----------------
__global__ void k_cvt(const float* __restrict__ x, __half* __restrict__ o, int total4) {
    int i = blockIdx.x * blockDim.x + threadIdx.x;
    if (i >= total4) return;
    float4 v = *(const float4*)&x[i * 4];
    __half2 h0 = __floats2half2_rn(v.x, v.y);
    __half2 h1 = __floats2half2_rn(v.z, v.w);
    uint2 u; u.x = *(unsigned*)&h0; u.y = *(unsigned*)&h1;
    *(uint2*)&o[i * 4] = u;
}

// ---------------- Tensor-core GEMM: C[M,128] = dinv[row]*(A[M,128] @ W) ------
__device__ __forceinline__ void mma16816(float c[4],
    unsigned a0, unsigned a1, unsigned a2, unsigned a3, unsigned b0, unsigned b1)
{
    asm volatile(
        "mma.sync.aligned.m16n8k16.row.col.f32.f16.f16.f32 "
        "{%0,%1,%2,%3}, {%4,%5,%6,%7}, {%8,%9}, {%0,%1,%2,%3};"
        : "+f"(c[0]), "+f"(c[1]), "+f"(c[2]), "+f"(c[3])
        : "r"(a0), "r"(a1), "r"(a2), "r"(a3), "r"(b0), "r"(b1));
}

__global__ __launch_bounds__(256, 1) void k_gemmTC(
    const __half* __restrict__ A, const __half* __restrict__ Wt,
    __half* __restrict__ C, int M)
{
    __shared__ __half As[128][136];            // 136-half pad -> conflict-free frags
    int tid = threadIdx.x;
    int wid = tid >> 5, lane = tid & 31;
    int group = lane >> 2, t = lane & 3;
    int row0 = blockIdx.x * 128;

    // Load A tile (fp16): 8 iterations of 16B per thread
    {
        int r = tid >> 4;                      // 0..15
        int c = (tid & 15) * 8;                // 0..120
        #pragma unroll
        for (int rr = 0; rr < 128; rr += 16) {
            int gr = row0 + rr + r;
            uint4 v = make_uint4(0u, 0u, 0u, 0u);
            if (gr < M) v = *(const uint4*)&A[(long long)gr * FDIM + c];
            *(uint4*)&As[rr + r][c] = v;
        }
    }
    __syncthreads();

    int warp_m = (wid & 3) * 32;               // 0,32,64,96
    int warp_n = (wid >> 2) * 64;              // 0,64

    float acc[2][8][4];
    #pragma unroll
    for (int mt = 0; mt < 2; mt++)
        #pragma unroll
        for (int nt = 0; nt < 8; nt++)
            #pragma unroll
            for (int q = 0; q < 4; q++) acc[mt][nt][q] = 0.0f;

    #pragma unroll
    for (int ks = 0; ks < 8; ks++) {
        int k0 = ks * 16;
        unsigned b[8][2];
        #pragma unroll
        for (int nt = 0; nt < 8; nt++) {
            const __half* wp = &Wt[(warp_n + nt * 8 + group) * FDIM + k0 + t * 2];
            b[nt][0] = *(const unsigned*)wp;
            b[nt][1] = *(const unsigned*)(wp + 8);
        }
        #pragma unroll
        for (int mt = 0; mt < 2; mt++) {
            int r = warp_m + mt * 16 + group;
            unsigned a0 = *(const unsigned*)&As[r][k0 + t * 2];
            unsigned a1 = *(const unsigned*)&As[r + 8][k0 + t * 2];
            unsigned a2 = *(const unsigned*)&As[r][k0 + t * 2 + 8];
            unsigned a3 = *(const unsigned*)&As[r + 8][k0 + t * 2 + 8];
            #pragma unroll
            for (int nt = 0; nt < 8; nt++)
                mma16816(acc[mt][nt], a0, a1, a2, a3, b[nt][0], b[nt][1]);
        }
    }

    // Epilogue: scale by dinv[row], store fp16
    #pragma unroll
    for (int mt = 0; mt < 2; mt++) {
        int rl = row0 + warp_m + mt * 16 + group;
        float dl = (rl < M)     ? g_dinv[rl]     : 0.0f;
        float dh = (rl + 8 < M) ? g_dinv[rl + 8] : 0.0f;
        #pragma unroll
        for (int nt = 0; nt < 8; nt++) {
            int cc = warp_n + nt * 8 + t * 2;
            if (rl < M) {
                __half2 h = __floats2half2_rn(acc[mt][nt][0] * dl, acc[mt][nt][1] * dl);
                *(unsigned*)&C[(long long)rl * FDIM + cc] = *(unsigned*)&h;
            }
            if (rl + 8 < M) {
                __half2 h = __floats2half2_rn(acc[mt][nt][2] * dh, acc[mt][nt][3] * dh);
                *(unsigned*)&C[(long long)(rl + 8) * FDIM + cc] = *(unsigned*)&h;
            }
        }
    }
}

// ---------------- Edge aggregation: half-warp per edge, LDG.128 --------------
__device__ __forceinline__ void addh8(float acc[8], uint4 v) {
    __half2* p = (__half2*)&v;
    #pragma unroll
    for (int q = 0; q < 4; q++) {
        float2 f = __half22float2(p[q]);
        acc[2 * q]     += f.x;
        acc[2 * q + 1] += f.y;
    }
}

__global__ __launch_bounds__(256) void k_gather128(
    const __half* __restrict__ hw, const float* __restrict__ bias,
    __half* __restrict__ out, int N, int do_relu)
{
    int warp = (blockIdx.x * blockDim.x + threadIdx.x) >> 5;
    int lane = threadIdx.x & 31;
    if (warp >= N) return;
    int h  = lane >> 4;          // half-warp id: 0/1
    int sl = lane & 15;          // sub-lane: feature chunk [sl*8, sl*8+8)
    int beg = g_rowptr[warp];
    int end = g_rowptr[warp + 1];

    float acc[8];
    #pragma unroll
    for (int j = 0; j < 8; j++) acc[j] = 0.0f;

    int base = beg;
    for (; base + 4 <= end; base += 4) {
        int s0 = g_srcs[base + h];
        int s1 = g_srcs[base + h + 2];
        uint4 v0 = *(const uint4*)&hw[(long long)s0 * FDIM + sl * 8];
        uint4 v1 = *(const uint4*)&hw[(long long)s1 * FDIM + sl * 8];
        addh8(acc, v0);
        addh8(acc, v1);
    }
    // tail (0..3 edges): h covers base+h and base+h+2
    if (base + h < end) {
        int s = g_srcs[base + h];
        uint4 v = *(const uint4*)&hw[(long long)s * FDIM + sl * 8];
        addh8(acc, v);
    }
    if (base + h + 2 < end) {
        int s = g_srcs[base + h + 2];
        uint4 v = *(const uint4*)&hw[(long long)s * FDIM + sl * 8];
        addh8(acc, v);
    }

    // combine the two half-warps
    #pragma unroll
    for (int j = 0; j < 8; j++) acc[j] += __shfl_xor_sync(0xFFFFFFFFu, acc[j], 16);

    if (h == 0) {
        float d = g_dinv[warp];
        float4 b0 = *(const float4*)&bias[sl * 8];
        float4 b1 = *(const float4*)&bias[sl * 8 + 4];
        float v[8];
        v[0] = fmaf(acc[0], d, b0.x); v[1] = fmaf(acc[1], d, b0.y);
        v[2] = fmaf(acc[2], d, b0.z); v[3] = fmaf(acc[3], d, b0.w);
        v[4] = fmaf(acc[4], d, b1.x); v[5] = fmaf(acc[5], d, b1.y);
        v[6] = fmaf(acc[6], d, b1.z); v[7] = fmaf(acc[7], d, b1.w);
        if (do_relu) {
            #pragma unroll
            for (int j = 0; j < 8; j++) v[j] = fmaxf(v[j], 0.0f);
        }
        __half2 h0 = __floats2half2_rn(v[0], v[1]);
        __half2 h1 = __floats2half2_rn(v[2], v[3]);
        __half2 h2 = __floats2half2_rn(v[4], v[5]);
        __half2 h3 = __floats2half2_rn(v[6], v[7]);
        uint4 u;
        u.x = *(unsigned*)&h0; u.y = *(unsigned*)&h1;
        u.z = *(unsigned*)&h2; u.w = *(unsigned*)&h3;
        *(uint4*)&out[(long long)warp * FDIM + sl * 8] = u;
    }
}

// ---------------- Last layer: C[M,10] = dinv[r]*(A[M,128](fp16) @ W[128,10]) --
__device__ __forceinline__ float4 ld_half4(const __half* base, long long s, int lane) {
    uint2 raw = *(const uint2*)&base[s * FDIM + lane * 4];
    __half2 a0 = *(__half2*)&raw.x;
    __half2 a1 = *(__half2*)&raw.y;
    float2 f0 = __half22float2(a0);
    float2 f1 = __half22float2(a1);
    return make_float4(f0.x, f0.y, f1.x, f1.y);
}

__global__ __launch_bounds__(256) void k_gemm10(
    const __half* __restrict__ A, const float* __restrict__ W,
    float* __restrict__ C, int M)
{
    __shared__ float Ws[128 * 10];
    int tid = threadIdx.x;
    for (int j = tid; j < 1280; j += 256) Ws[j] = W[j];
    __syncthreads();
    int r = blockIdx.x * 8 + (tid >> 5);
    int lane = tid & 31;
    if (r >= M) return;
    float4 a = ld_half4(A, r, lane);
    float acc[10];
    #pragma unroll
    for (int c = 0; c < 10; c++) {
        acc[c] = a.x * Ws[(lane * 4 + 0) * 10 + c]
               + a.y * Ws[(lane * 4 + 1) * 10 + c]
               + a.z * Ws[(lane * 4 + 2) * 10 + c]
               + a.w * Ws[(lane * 4 + 3) * 10 + c];
    }
    #pragma unroll
    for (int off = 16; off > 0; off >>= 1)
        #pragma unroll
        for (int c = 0; c < 10; c++)
            acc[c] += __shfl_xor_sync(0xFFFFFFFFu, acc[c], off);
    float v = 0.0f;
    #pragma unroll
    for (int c = 0; c < 10; c++) v = (lane == c) ? acc[c] : v;
    if (lane < 10) C[(long long)r * 10 + lane] = v * g_dinv[r];
}

__global__ __launch_bounds__(256) void k_gather10(
    const float* __restrict__ hw, const float* __restrict__ bias,
    float* __restrict__ out, int N)
{
    int warp = (blockIdx.x * blockDim.x + threadIdx.x) >> 5;
    int lane = threadIdx.x & 31;
    if (warp >= N) return;
    int beg = g_rowptr[warp];
    int end = g_rowptr[warp + 1];
    float acc = 0.0f;
    for (int e = beg; e < end; e++) {
        int s = g_srcs[e];
        float v = (lane < 10) ? hw[(long long)s * 10 + lane] : 0.0f;
        acc += v;
    }
    if (lane < 10)
        out[(long long)warp * 10 + lane] = fmaf(acc, g_dinv[warp], bias[lane]);
}

// ---------------- Pooling + log_softmax ----------------
__global__ void k_pool(const int* __restrict__ batch,
                       const float* __restrict__ h10, int N)
{
    int i = blockIdx.x * blockDim.x + threadIdx.x;
    if (i >= N) return;
    int g = batch[i];
    const float* p = &h10[(long long)i * 10];
    #pragma unroll
    for (int c = 0; c < 10; c++) atomicAdd(&g_pool[g * 10 + c], p[c]);
    atomicAdd(&g_cnt[g], 1.0f);
}

__global__ void k_final(float* __restrict__ out) {
    int g = blockIdx.x * blockDim.x + threadIdx.x;
    if (g >= NGRAPH) return;
    float cnt = fmaxf(g_cnt[g], 1.0f);
    float v[10];
    float m = -1e30f;
    #pragma unroll
    for (int c = 0; c < 10; c++) { v[c] = g_pool[g * 10 + c] / cnt; m = fmaxf(m, v[c]); }
    float s = 0.0f;
    #pragma unroll
    for (int c = 0; c < 10; c++) s += __expf(v[c] - m);
    float lse = m + __logf(s);
    #pragma unroll
    for (int c = 0; c < 10; c++) out[g * 10 + c] = v[c] - lse;
}

// ---------------- Launch ----------------
extern "C" void kernel_launch(void* const* d_in, const int* in_sizes, int n_in,
                              void* d_out, int out_size)
{
    const float* x     = (const float*)d_in[0];
    const int*   ei    = (const int*)d_in[1];     // int32
    const int*   batch = (const int*)d_in[2];     // int32
    const float* W_in  = (const float*)d_in[3];
    const float* b_in  = (const float*)d_in[4];
    const float* W_h0  = (const float*)d_in[5];
    const float* b_h0  = (const float*)d_in[6];
    const float* W_h1  = (const float*)d_in[7];
    const float* b_h1  = (const float*)d_in[8];
    const float* W_out = (const float*)d_in[9];
    const float* b_out = (const float*)d_in[10];
    float* out = (float*)d_out;

    int N = in_sizes[0] / FDIM;       // 100000
    int E = in_sizes[1] / 2;          // 3200000

    __half *f16a, *f16b, *Wt;
    float *h10a, *h10b;
    cudaGetSymbolAddress((void**)&f16a, g_f16a);
    cudaGetSymbolAddress((void**)&f16b, g_f16b);
    cudaGetSymbolAddress((void**)&Wt,   g_Wt);
    cudaGetSymbolAddress((void**)&h10a, g_h10a);
    cudaGetSymbolAddress((void**)&h10b, g_h10b);

    int tb = 256;
    int gbN = (N + tb - 1) / tb;
    int gbE = (E + tb - 1) / tb;
    int nb  = (N + 1023) / 1024;

    // Graph preprocessing (CSR by dst, self-loops in slot 0)
    k_init<<<gbN, tb>>>(N);
    k_count<<<gbE, tb>>>(ei, E);
    k_dinv<<<gbN, tb>>>(N);
    k_scan_block<<<nb, 1024>>>(N);
    k_scan_sums<<<1, 32>>>(nb, N);
    k_scan_add<<<gbN, tb>>>(N);
    k_selfloop<<<gbN, tb>>>(N);
    k_fill<<<gbE, tb>>>(ei, E);

    // Weight conversion (tiny) + x -> fp16
    k_prepW<<<64, 256>>>(W_in, Wt);
    k_prepW<<<64, 256>>>(W_h0, Wt + FDIM * FDIM);
    k_prepW<<<64, 256>>>(W_h1, Wt + 2 * FDIM * FDIM);
    int total4 = N * FDIM / 4;
    k_cvt<<<(total4 + 255) / 256, 256>>>(x, f16a, total4);

    int gemmBlocks   = (N + 127) / 128;
    int gatherBlocks = (N + 7) / 8;    // 8 warps per 256-thread block

    // Layer 1
    k_gemmTC<<<gemmBlocks, 256>>>(f16a, Wt, f16b, N);
    k_gather128<<<gatherBlocks, 256>>>(f16b, b_in, f16a, N, 1);
    // Layer 2
    k_gemmTC<<<gemmBlocks, 256>>>(f16a, Wt + FDIM * FDIM, f16b, N);
    k_gather128<<<gatherBlocks, 256>>>(f16b, b_h0, f16a, N, 1);
    // Layer 3
    k_gemmTC<<<gemmBlocks, 256>>>(f16a, Wt + 2 * FDIM * FDIM, f16b, N);
    k_gather128<<<gatherBlocks, 256>>>(f16b, b_h1, f16a, N, 1);
    // Output layer (C=10, no relu)
    k_gemm10<<<(N + 7) / 8, 256>>>(f16a, W_out, h10a, N);
    k_gather10<<<gatherBlocks, 256>>>(h10a, b_out, h10b, N);

    // Mean pool + log_softmax
    k_pool<<<gbN, tb>>>(batch, h10b, N);
    k_final<<<(NGRAPH + 255) / 256, 256>>>(out);
}

// round 11
// speedup vs baseline: 1.7489x; 1.0628x over previous
#include <cuda_runtime.h>
#include <cuda_fp16.h>

// ---------------- Problem constants ----------------
#define NMAX   100000
#define EMAX   3200000
#define ETOT   (EMAX + NMAX)   // edges + self loops
#define FDIM   128
#define CDIM   10
#define NGRAPH 512

// ---------------- Device scratch (static, allocation-free) ----------------
__device__ __half g_f16a[NMAX * FDIM];     // gather output (GEMM input)
__device__ __half g_f16b[NMAX * FDIM];     // GEMM output (gather input, dinv-prescaled)
__device__ __half g_Wt  [3 * FDIM * FDIM]; // fp16 transposed weights Wt[n][k]
__device__ __half g_h10h[NMAX * 16];       // last-layer GEMM output (fp16, stride 16)
__device__ float  g_h10b[NMAX * 16];       // last-layer aggregated (fp32, stride 16)
__device__ int    g_srcs[ETOT];            // CSR-by-dst src indices (self loop slot 0)
__device__ int    g_rowptr[NMAX + 1];
__device__ int    g_cursor[NMAX];
__device__ int    g_deg [NMAX];
__device__ float  g_dinv[NMAX];
__device__ int    g_bsums[256];
__device__ int    g_gstart[NGRAPH + 1];

// ---------------- Graph preprocessing ----------------

__global__ void k_init(int N) {
    int i = blockIdx.x * blockDim.x + threadIdx.x;
    if (i < N) g_deg[i] = 1;                    // self loop contributes 1
}

__global__ void k_count(const int* __restrict__ ei, int E) {
    int e = blockIdx.x * blockDim.x + threadIdx.x;
    if (e >= E) return;
    atomicAdd(&g_deg[ei[E + e]], 1);
}

__global__ void k_scan_block(int N) {
    __shared__ int sh[1024];
    int tid = threadIdx.x;
    int i = blockIdx.x * 1024 + tid;
    int v = (i < N) ? g_deg[i] : 0;
    sh[tid] = v;
    __syncthreads();
    for (int off = 1; off < 1024; off <<= 1) {
        int t = (tid >= off) ? sh[tid - off] : 0;
        __syncthreads();
        sh[tid] += t;
        __syncthreads();
    }
    if (i < N) g_rowptr[i] = sh[tid] - v;
    if (tid == 1023) g_bsums[blockIdx.x] = sh[1023];
}

__global__ void k_scan_sums(int nb, int N) {
    if (threadIdx.x == 0 && blockIdx.x == 0) {
        int run = 0;
        for (int b = 0; b < nb; b++) { int t = g_bsums[b]; g_bsums[b] = run; run += t; }
        g_rowptr[N] = run;
    }
}

// Fused: scan_add + dinv + selfloop (self loop in slot 0, cursor after it).
__global__ void k_finalize(int N) {
    int i = blockIdx.x * blockDim.x + threadIdx.x;
    if (i >= N) return;
    int rp = g_rowptr[i] + g_bsums[i >> 10];
    g_rowptr[i] = rp;
    g_dinv[i] = rsqrtf((float)g_deg[i]);
    g_srcs[rp] = i;
    g_cursor[i] = rp + 1;
}

__global__ void k_fill(const int* __restrict__ ei, int E) {
    int e = blockIdx.x * blockDim.x + threadIdx.x;
    if (e >= E) return;
    int s = ei[e];
    int d = ei[E + e];
    int p = atomicAdd(&g_cursor[d], 1);
    g_srcs[p] = s;
}

// Graph boundaries from sorted batch: g_gstart[g] = first node of graph g.
__global__ void k_gbound(const int* __restrict__ batch, int N) {
    int i = blockIdx.x * blockDim.x + threadIdx.x;
    if (i >= N) return;
    int cur = batch[i];
    int prev = (i == 0) ? -1 : batch[i - 1];
    for (int g = prev + 1; g <= cur; g++) g_gstart[g] = i;
    if (i == N - 1)
        for (int g = cur + 1; g <= NGRAPH; g++) g_gstart[g] = N;
}

// ---------------- Weight prep: 3x (W fp32 [k][n] -> Wt fp16 [n][k]) ----------
__global__ void k_prepW3(const float* __restrict__ W0, const float* __restrict__ W1,
                         const float* __restrict__ W2, __half* __restrict__ Wt) {
    int idx = blockIdx.x * blockDim.x + threadIdx.x;   // 3*16384
    if (idx >= 3 * FDIM * FDIM) return;
    int m = idx / (FDIM * FDIM);
    int r = idx - m * (FDIM * FDIM);
    const float* W = (m == 0) ? W0 : (m == 1) ? W1 : W2;
    int n = r >> 7, k = r & 127;
    Wt[m * FDIM * FDIM + n * FDIM + k] = __float2half(W[k * FDIM + n]);
}

// ---------------- Tensor-core GEMM: C[M,128] = dinv[row]*(A[M,128] @ W) ------
__device__ __forceinline__ void mma16816(float c[4],
    unsigned a0, unsigned a1, unsigned a2, unsigned a3, unsigned b0, unsigned b1)
{
    asm volatile(
        "mma.sync.aligned.m16n8k16.row.col.f32.f16.f16.f32 "
        "{%0,%1,%2,%3}, {%4,%5,%6,%7}, {%8,%9}, {%0,%1,%2,%3};"
        : "+f"(c[0]), "+f"(c[1]), "+f"(c[2]), "+f"(c[3])
        : "r"(a0), "r"(a1), "r"(a2), "r"(a3), "r"(b0), "r"(b1));
}

template<bool F32IN>
__global__ __launch_bounds__(256, 1) void k_gemmTC(
    const void* __restrict__ Ain, const __half* __restrict__ Wt,
    __half* __restrict__ C, int M)
{
    __shared__ __half As[128][136];            // 136-half pad -> conflict-free frags
    int tid = threadIdx.x;
    int wid = tid >> 5, lane = tid & 31;
    int group = lane >> 2, t = lane & 3;
    int row0 = blockIdx.x * 128;

    // Load A tile into fp16 smem (converting from fp32 for layer 1)
    {
        int r = tid >> 4;                      // 0..15
        int c = (tid & 15) * 8;                // 0..120
        #pragma unroll
        for (int rr = 0; rr < 128; rr += 16) {
            int gr = row0 + rr + r;
            if (F32IN) {
                const float* A32 = (const float*)Ain;
                float4 v0 = make_float4(0.f, 0.f, 0.f, 0.f);
                float4 v1 = v0;
                if (gr < M) {
                    v0 = *(const float4*)&A32[(long long)gr * FDIM + c];
                    v1 = *(const float4*)&A32[(long long)gr * FDIM + c + 4];
                }
                __half2 h0 = __floats2half2_rn(v0.x, v0.y);
                __half2 h1 = __floats2half2_rn(v0.z, v0.w);
                __half2 h2 = __floats2half2_rn(v1.x, v1.y);
                __half2 h3 = __floats2half2_rn(v1.z, v1.w);
                uint4 u;
                u.x = *(unsigned*)&h0; u.y = *(unsigned*)&h1;
                u.z = *(unsigned*)&h2; u.w = *(unsigned*)&h3;
                *(uint4*)&As[rr + r][c] = u;
            } else {
                const __half* A16 = (const __half*)Ain;
                uint4 v = make_uint4(0u, 0u, 0u, 0u);
                if (gr < M) v = *(const uint4*)&A16[(long long)gr * FDIM + c];
                *(uint4*)&As[rr + r][c] = v;
            }
        }
    }
    __syncthreads();

    int warp_m = (wid & 3) * 32;               // 0,32,64,96
    int warp_n = (wid >> 2) * 64;              // 0,64

    float acc[2][8][4];
    #pragma unroll
    for (int mt = 0; mt < 2; mt++)
        #pragma unroll
        for (int nt = 0; nt < 8; nt++)
            #pragma unroll
            for (int q = 0; q < 4; q++) acc[mt][nt][q] = 0.0f;

    #pragma unroll
    for (int ks = 0; ks < 8; ks++) {
        int k0 = ks * 16;
        unsigned b[8][2];
        #pragma unroll
        for (int nt = 0; nt < 8; nt++) {
            const __half* wp = &Wt[(warp_n + nt * 8 + group) * FDIM + k0 + t * 2];
            b[nt][0] = *(const unsigned*)wp;
            b[nt][1] = *(const unsigned*)(wp + 8);
        }
        #pragma unroll
        for (int mt = 0; mt < 2; mt++) {
            int r = warp_m + mt * 16 + group;
            unsigned a0 = *(const unsigned*)&As[r][k0 + t * 2];
            unsigned a1 = *(const unsigned*)&As[r + 8][k0 + t * 2];
            unsigned a2 = *(const unsigned*)&As[r][k0 + t * 2 + 8];
            unsigned a3 = *(const unsigned*)&As[r + 8][k0 + t * 2 + 8];
            #pragma unroll
            for (int nt = 0; nt < 8; nt++)
                mma16816(acc[mt][nt], a0, a1, a2, a3, b[nt][0], b[nt][1]);
        }
    }

    // Epilogue: scale by dinv[row], store fp16
    #pragma unroll
    for (int mt = 0; mt < 2; mt++) {
        int rl = row0 + warp_m + mt * 16 + group;
        float dl = (rl < M)     ? g_dinv[rl]     : 0.0f;
        float dh = (rl + 8 < M) ? g_dinv[rl + 8] : 0.0f;
        #pragma unroll
        for (int nt = 0; nt < 8; nt++) {
            int cc = warp_n + nt * 8 + t * 2;
            if (rl < M) {
                __half2 h = __floats2half2_rn(acc[mt][nt][0] * dl, acc[mt][nt][1] * dl);
                *(unsigned*)&C[(long long)rl * FDIM + cc] = *(unsigned*)&h;
            }
            if (rl + 8 < M) {
                __half2 h = __floats2half2_rn(acc[mt][nt][2] * dh, acc[mt][nt][3] * dh);
                *(unsigned*)&C[(long long)(rl + 8) * FDIM + cc] = *(unsigned*)&h;
            }
        }
    }
}

// ---------------- Edge aggregation: half-warp per edge, LDG.128 --------------
__device__ __forceinline__ void addh8(float acc[8], uint4 v) {
    __half2* p = (__half2*)&v;
    #pragma unroll
    for (int q = 0; q < 4; q++) {
        float2 f = __half22float2(p[q]);
        acc[2 * q]     += f.x;
        acc[2 * q + 1] += f.y;
    }
}

__global__ __launch_bounds__(256) void k_gather128(
    const __half* __restrict__ hw, const float* __restrict__ bias,
    __half* __restrict__ out, int N, int do_relu)
{
    int warp = (blockIdx.x * blockDim.x + threadIdx.x) >> 5;
    int lane = threadIdx.x & 31;
    if (warp >= N) return;
    int h  = lane >> 4;          // half-warp id: 0/1
    int sl = lane & 15;          // sub-lane: feature chunk [sl*8, sl*8+8)
    int beg = g_rowptr[warp];
    int end = g_rowptr[warp + 1];

    float acc[8];
    #pragma unroll
    for (int j = 0; j < 8; j++) acc[j] = 0.0f;

    int base = beg;
    // 8 edges / iter: 4 independent LDG.128 per lane in flight
    for (; base + 8 <= end; base += 8) {
        int s0 = g_srcs[base + h];
        int s1 = g_srcs[base + h + 2];
        int s2 = g_srcs[base + h + 4];
        int s3 = g_srcs[base + h + 6];
        uint4 v0 = *(const uint4*)&hw[(long long)s0 * FDIM + sl * 8];
        uint4 v1 = *(const uint4*)&hw[(long long)s1 * FDIM + sl * 8];
        uint4 v2 = *(const uint4*)&hw[(long long)s2 * FDIM + sl * 8];
        uint4 v3 = *(const uint4*)&hw[(long long)s3 * FDIM + sl * 8];
        addh8(acc, v0); addh8(acc, v1); addh8(acc, v2); addh8(acc, v3);
    }
    for (; base + 4 <= end; base += 4) {
        int s0 = g_srcs[base + h];
        int s1 = g_srcs[base + h + 2];
        uint4 v0 = *(const uint4*)&hw[(long long)s0 * FDIM + sl * 8];
        uint4 v1 = *(const uint4*)&hw[(long long)s1 * FDIM + sl * 8];
        addh8(acc, v0); addh8(acc, v1);
    }
    if (base + h < end) {
        int s = g_srcs[base + h];
        uint4 v = *(const uint4*)&hw[(long long)s * FDIM + sl * 8];
        addh8(acc, v);
    }
    if (base + h + 2 < end) {
        int s = g_srcs[base + h + 2];
        uint4 v = *(const uint4*)&hw[(long long)s * FDIM + sl * 8];
        addh8(acc, v);
    }

    // combine the two half-warps
    #pragma unroll
    for (int j = 0; j < 8; j++) acc[j] += __shfl_xor_sync(0xFFFFFFFFu, acc[j], 16);

    if (h == 0) {
        float d = g_dinv[warp];
        float4 b0 = *(const float4*)&bias[sl * 8];
        float4 b1 = *(const float4*)&bias[sl * 8 + 4];
        float v[8];
        v[0] = fmaf(acc[0], d, b0.x); v[1] = fmaf(acc[1], d, b0.y);
        v[2] = fmaf(acc[2], d, b0.z); v[3] = fmaf(acc[3], d, b0.w);
        v[4] = fmaf(acc[4], d, b1.x); v[5] = fmaf(acc[5], d, b1.y);
        v[6] = fmaf(acc[6], d, b1.z); v[7] = fmaf(acc[7], d, b1.w);
        if (do_relu) {
            #pragma unroll
            for (int j = 0; j < 8; j++) v[j] = fmaxf(v[j], 0.0f);
        }
        __half2 h0 = __floats2half2_rn(v[0], v[1]);
        __half2 h1 = __floats2half2_rn(v[2], v[3]);
        __half2 h2 = __floats2half2_rn(v[4], v[5]);
        __half2 h3 = __floats2half2_rn(v[6], v[7]);
        uint4 u;
        u.x = *(unsigned*)&h0; u.y = *(unsigned*)&h1;
        u.z = *(unsigned*)&h2; u.w = *(unsigned*)&h3;
        *(uint4*)&out[(long long)warp * FDIM + sl * 8] = u;
    }
}

// ---------------- Last layer: fp16 rows, stride 16 (32B = one sector) --------
__device__ __forceinline__ float4 ld_half4(const __half* base, long long s, int lane) {
    uint2 raw = *(const uint2*)&base[s * FDIM + lane * 4];
    __half2 a0 = *(__half2*)&raw.x;
    __half2 a1 = *(__half2*)&raw.y;
    float2 f0 = __half22float2(a0);
    float2 f1 = __half22float2(a1);
    return make_float4(f0.x, f0.y, f1.x, f1.y);
}

__global__ __launch_bounds__(256) void k_gemm10(
    const __half* __restrict__ A, const float* __restrict__ W,
    __half* __restrict__ C, int M)
{
    __shared__ float Ws[128 * 10];
    int tid = threadIdx.x;
    for (int j = tid; j < 1280; j += 256) Ws[j] = W[j];
    __syncthreads();
    int r = blockIdx.x * 8 + (tid >> 5);
    int lane = tid & 31;
    if (r >= M) return;
    float4 a = ld_half4(A, r, lane);
    float acc[10];
    #pragma unroll
    for (int c = 0; c < 10; c++) {
        acc[c] = a.x * Ws[(lane * 4 + 0) * 10 + c]
               + a.y * Ws[(lane * 4 + 1) * 10 + c]
               + a.z * Ws[(lane * 4 + 2) * 10 + c]
               + a.w * Ws[(lane * 4 + 3) * 10 + c];
    }
    #pragma unroll
    for (int off = 16; off > 0; off >>= 1)
        #pragma unroll
        for (int c = 0; c < 10; c++)
            acc[c] += __shfl_xor_sync(0xFFFFFFFFu, acc[c], off);
    float v = 0.0f;
    #pragma unroll
    for (int c = 0; c < 10; c++) v = (lane == c) ? acc[c] : v;
    if (lane < 10) C[(long long)r * 16 + lane] = __float2half(v * g_dinv[r]);
    if (lane >= 10 && lane < 16) C[(long long)r * 16 + lane] = __float2half(0.0f);
}

__global__ __launch_bounds__(256) void k_gather10(
    const __half* __restrict__ hw, const float* __restrict__ bias,
    float* __restrict__ out, int N)
{
    int warp = (blockIdx.x * blockDim.x + threadIdx.x) >> 5;
    int lane = threadIdx.x & 31;
    if (warp >= N) return;
    int beg = g_rowptr[warp];
    int end = g_rowptr[warp + 1];
    float acc = 0.0f;
    #pragma unroll 4
    for (int e = beg; e < end; e++) {
        int s = g_srcs[e];
        float v = (lane < 10) ? __half2float(hw[(long long)s * 16 + lane]) : 0.0f;
        acc += v;
    }
    if (lane < 10)
        out[(long long)warp * 16 + lane] = fmaf(acc, g_dinv[warp], bias[lane]);
}

// ---------------- Pool (one block per graph) + log_softmax, fused ------------
__global__ __launch_bounds__(128) void k_poolfinal(float* __restrict__ out) {
    int g = blockIdx.x;
    int beg = g_gstart[g], end = g_gstart[g + 1];
    int tid = threadIdx.x;

    float acc[10];
    #pragma unroll
    for (int c = 0; c < 10; c++) acc[c] = 0.0f;
    for (int i = beg + tid; i < end; i += 128) {
        const float* p = &g_h10b[(long long)i * 16];
        #pragma unroll
        for (int c = 0; c < 10; c++) acc[c] += p[c];
    }
    #pragma unroll
    for (int off = 16; off > 0; off >>= 1)
        #pragma unroll
        for (int c = 0; c < 10; c++)
            acc[c] += __shfl_xor_sync(0xFFFFFFFFu, acc[c], off);

    __shared__ float sh[4][10];
    if ((tid & 31) == 0) {
        #pragma unroll
        for (int c = 0; c < 10; c++) sh[tid >> 5][c] = acc[c];
    }
    __syncthreads();
    if (tid == 0) {
        float cnt = fmaxf((float)(end - beg), 1.0f);
        float v[10];
        float m = -1e30f;
        #pragma unroll
        for (int c = 0; c < 10; c++) {
            v[c] = (sh[0][c] + sh[1][c] + sh[2][c] + sh[3][c]) / cnt;
            m = fmaxf(m, v[c]);
        }
        float s = 0.0f;
        #pragma unroll
        for (int c = 0; c < 10; c++) s += __expf(v[c] - m);
        float lse = m + __logf(s);
        #pragma unroll
        for (int c = 0; c < 10; c++) out[g * 10 + c] = v[c] - lse;
    }
}

// ---------------- Launch ----------------
extern "C" void kernel_launch(void* const* d_in, const int* in_sizes, int n_in,
                              void* d_out, int out_size)
{
    const float* x     = (const float*)d_in[0];
    const int*   ei    = (const int*)d_in[1];     // int32
    const int*   batch = (const int*)d_in[2];     // int32
    const float* W_in  = (const float*)d_in[3];
    const float* b_in  = (const float*)d_in[4];
    const float* W_h0  = (const float*)d_in[5];
    const float* b_h0  = (const float*)d_in[6];
    const float* W_h1  = (const float*)d_in[7];
    const float* b_h1  = (const float*)d_in[8];
    const float* W_out = (const float*)d_in[9];
    const float* b_out = (const float*)d_in[10];
    float* out = (float*)d_out;

    int N = in_sizes[0] / FDIM;       // 100000
    int E = in_sizes[1] / 2;          // 3200000

    __half *f16a, *f16b, *Wt, *h10h;
    float *h10b;
    cudaGetSymbolAddress((void**)&f16a, g_f16a);
    cudaGetSymbolAddress((void**)&f16b, g_f16b);
    cudaGetSymbolAddress((void**)&Wt,   g_Wt);
    cudaGetSymbolAddress((void**)&h10h, g_h10h);
    cudaGetSymbolAddress((void**)&h10b, g_h10b);

    int tb = 256;
    int gbN = (N + tb - 1) / tb;
    int gbE = (E + tb - 1) / tb;
    int nb  = (N + 1023) / 1024;

    // Graph preprocessing (CSR by dst, self-loops in slot 0)
    k_init<<<gbN, tb>>>(N);
    k_count<<<gbE, tb>>>(ei, E);
    k_scan_block<<<nb, 1024>>>(N);
    k_scan_sums<<<1, 32>>>(nb, N);
    k_finalize<<<gbN, tb>>>(N);
    k_fill<<<gbE, tb>>>(ei, E);
    k_gbound<<<gbN, tb>>>(batch, N);

    // Weight conversion (one launch for all three)
    k_prepW3<<<(3 * FDIM * FDIM + 255) / 256, 256>>>(W_in, W_h0, W_h1, Wt);

    int gemmBlocks   = (N + 127) / 128;
    int gatherBlocks = (N + 7) / 8;    // 8 warps per 256-thread block

    // Layer 1 (fp32 input, converts in-kernel)
    k_gemmTC<true><<<gemmBlocks, 256>>>(x, Wt, f16b, N);
    k_gather128<<<gatherBlocks, 256>>>(f16b, b_in, f16a, N, 1);
    // Layer 2
    k_gemmTC<false><<<gemmBlocks, 256>>>(f16a, Wt + FDIM * FDIM, f16b, N);
    k_gather128<<<gatherBlocks, 256>>>(f16b, b_h0, f16a, N, 1);
    // Layer 3
    k_gemmTC<false><<<gemmBlocks, 256>>>(f16a, Wt + 2 * FDIM * FDIM, f16b, N);
    k_gather128<<<gatherBlocks, 256>>>(f16b, b_h1, f16a, N, 1);
    // Output layer (C=10, no relu), fp16 stride-16 rows
    k_gemm10<<<(N + 7) / 8, 256>>>(f16a, W_out, h10h, N);
    k_gather10<<<gatherBlocks, 256>>>(h10h, b_out, h10b, N);

    // Fused mean-pool + log_softmax (one block per graph)
    k_poolfinal<<<NGRAPH, 128>>>(out);
}

// round 12
// speedup vs baseline: 1.8961x; 1.0841x over previous
#include <cuda_runtime.h>
#include <cuda_fp16.h>

// ---------------- Problem constants ----------------
#define NMAX   100000
#define EMAX   3200000
#define ETOT   (EMAX + NMAX)   // edges + self loops
#define FDIM   128
#define CDIM   10
#define NGRAPH 512

// ---------------- Device scratch (static, allocation-free) ----------------
__device__ __half g_f16a[NMAX * FDIM];     // gather output (GEMM input)
__device__ __half g_f16b[NMAX * FDIM];     // GEMM output (gather input, dinv-prescaled)
__device__ __half g_Wt  [3 * FDIM * FDIM]; // fp16 transposed weights Wt[n][k]
__device__ __half g_h10h[NMAX * 16];       // last-layer GEMM output (fp16, stride 16)
__device__ float  g_h10b[NMAX * 16];       // last-layer aggregated (fp32, stride 16)
__device__ int    g_srcs[ETOT];            // CSR-by-dst src indices (self loop slot 0)
__device__ int    g_rowptr[NMAX + 1];
__device__ int    g_cursor[NMAX];
__device__ int    g_deg [NMAX];
__device__ float  g_dinv[NMAX];
__device__ int    g_bsums[256];
__device__ int    g_gstart[NGRAPH + 1];

// ---------------- Graph preprocessing ----------------

__global__ void k_init(int N) {
    int i = blockIdx.x * blockDim.x + threadIdx.x;
    if (i < N) g_deg[i] = 1;                    // self loop contributes 1
}

__global__ void k_count(const int* __restrict__ ei, int E) {
    int e = blockIdx.x * blockDim.x + threadIdx.x;
    if (e >= E) return;
    atomicAdd(&g_deg[ei[E + e]], 1);
}

// dinv split out so the layer-1 GEMM (side stream) can start early.
__global__ void k_dinv(int N) {
    int i = blockIdx.x * blockDim.x + threadIdx.x;
    if (i >= N) return;
    g_dinv[i] = rsqrtf((float)g_deg[i]);
}

__global__ void k_scan_block(int N) {
    __shared__ int sh[1024];
    int tid = threadIdx.x;
    int i = blockIdx.x * 1024 + tid;
    int v = (i < N) ? g_deg[i] : 0;
    sh[tid] = v;
    __syncthreads();
    for (int off = 1; off < 1024; off <<= 1) {
        int t = (tid >= off) ? sh[tid - off] : 0;
        __syncthreads();
        sh[tid] += t;
        __syncthreads();
    }
    if (i < N) g_rowptr[i] = sh[tid] - v;
    if (tid == 1023) g_bsums[blockIdx.x] = sh[1023];
}

// Parallel scan of <=128 block sums (one 128-thread block, Hillis-Steele).
__global__ void k_scan_sums(int nb, int N) {
    __shared__ int sh[128];
    int tid = threadIdx.x;
    int v = (tid < nb) ? g_bsums[tid] : 0;
    sh[tid] = v;
    __syncthreads();
    #pragma unroll
    for (int off = 1; off < 128; off <<= 1) {
        int t = (tid >= off) ? sh[tid - off] : 0;
        __syncthreads();
        sh[tid] += t;
        __syncthreads();
    }
    if (tid < nb) g_bsums[tid] = sh[tid] - v;   // exclusive
    if (tid == nb - 1) g_rowptr[N] = sh[tid];   // total
}

// Fused: scan_add + selfloop (self loop in slot 0, cursor after it).
__global__ void k_finalize(int N) {
    int i = blockIdx.x * blockDim.x + threadIdx.x;
    if (i >= N) return;
    int rp = g_rowptr[i] + g_bsums[i >> 10];
    g_rowptr[i] = rp;
    g_srcs[rp] = i;
    g_cursor[i] = rp + 1;
}

__global__ void k_fill(const int* __restrict__ ei, int E) {
    int e = blockIdx.x * blockDim.x + threadIdx.x;
    if (e >= E) return;
    int s = ei[e];
    int d = ei[E + e];
    int p = atomicAdd(&g_cursor[d], 1);
    g_srcs[p] = s;
}

// Graph boundaries from sorted batch: g_gstart[g] = first node of graph g.
__global__ void k_gbound(const int* __restrict__ batch, int N) {
    int i = blockIdx.x * blockDim.x + threadIdx.x;
    if (i >= N) return;
    int cur = batch[i];
    int prev = (i == 0) ? -1 : batch[i - 1];
    for (int g = prev + 1; g <= cur; g++) g_gstart[g] = i;
    if (i == N - 1)
        for (int g = cur + 1; g <= NGRAPH; g++) g_gstart[g] = N;
}

// ---------------- Weight prep: 3x (W fp32 [k][n] -> Wt fp16 [n][k]) ----------
__global__ void k_prepW3(const float* __restrict__ W0, const float* __restrict__ W1,
                         const float* __restrict__ W2, __half* __restrict__ Wt) {
    int idx = blockIdx.x * blockDim.x + threadIdx.x;   // 3*16384
    if (idx >= 3 * FDIM * FDIM) return;
    int m = idx / (FDIM * FDIM);
    int r = idx - m * (FDIM * FDIM);
    const float* W = (m == 0) ? W0 : (m == 1) ? W1 : W2;
    int n = r >> 7, k = r & 127;
    Wt[m * FDIM * FDIM + n * FDIM + k] = __float2half(W[k * FDIM + n]);
}

// ---------------- Tensor-core GEMM: C[M,128] = dinv[row]*(A[M,128] @ W) ------
__device__ __forceinline__ void mma16816(float c[4],
    unsigned a0, unsigned a1, unsigned a2, unsigned a3, unsigned b0, unsigned b1)
{
    asm volatile(
        "mma.sync.aligned.m16n8k16.row.col.f32.f16.f16.f32 "
        "{%0,%1,%2,%3}, {%4,%5,%6,%7}, {%8,%9}, {%0,%1,%2,%3};"
        : "+f"(c[0]), "+f"(c[1]), "+f"(c[2]), "+f"(c[3])
        : "r"(a0), "r"(a1), "r"(a2), "r"(a3), "r"(b0), "r"(b1));
}

template<bool F32IN>
__global__ __launch_bounds__(256, 1) void k_gemmTC(
    const void* __restrict__ Ain, const __half* __restrict__ Wt,
    __half* __restrict__ C, int M)
{
    __shared__ __half As[128][136];            // 136-half pad -> conflict-free frags
    int tid = threadIdx.x;
    int wid = tid >> 5, lane = tid & 31;
    int group = lane >> 2, t = lane & 3;
    int row0 = blockIdx.x * 128;

    // Load A tile into fp16 smem (converting from fp32 for layer 1)
    {
        int r = tid >> 4;                      // 0..15
        int c = (tid & 15) * 8;                // 0..120
        #pragma unroll
        for (int rr = 0; rr < 128; rr += 16) {
            int gr = row0 + rr + r;
            if (F32IN) {
                const float* A32 = (const float*)Ain;
                float4 v0 = make_float4(0.f, 0.f, 0.f, 0.f);
                float4 v1 = v0;
                if (gr < M) {
                    v0 = *(const float4*)&A32[(long long)gr * FDIM + c];
                    v1 = *(const float4*)&A32[(long long)gr * FDIM + c + 4];
                }
                __half2 h0 = __floats2half2_rn(v0.x, v0.y);
                __half2 h1 = __floats2half2_rn(v0.z, v0.w);
                __half2 h2 = __floats2half2_rn(v1.x, v1.y);
                __half2 h3 = __floats2half2_rn(v1.z, v1.w);
                uint4 u;
                u.x = *(unsigned*)&h0; u.y = *(unsigned*)&h1;
                u.z = *(unsigned*)&h2; u.w = *(unsigned*)&h3;
                *(uint4*)&As[rr + r][c] = u;
            } else {
                const __half* A16 = (const __half*)Ain;
                uint4 v = make_uint4(0u, 0u, 0u, 0u);
                if (gr < M) v = *(const uint4*)&A16[(long long)gr * FDIM + c];
                *(uint4*)&As[rr + r][c] = v;
            }
        }
    }
    __syncthreads();

    int warp_m = (wid & 3) * 32;               // 0,32,64,96
    int warp_n = (wid >> 2) * 64;              // 0,64

    float acc[2][8][4];
    #pragma unroll
    for (int mt = 0; mt < 2; mt++)
        #pragma unroll
        for (int nt = 0; nt < 8; nt++)
            #pragma unroll
            for (int q = 0; q < 4; q++) acc[mt][nt][q] = 0.0f;

    #pragma unroll
    for (int ks = 0; ks < 8; ks++) {
        int k0 = ks * 16;
        unsigned b[8][2];
        #pragma unroll
        for (int nt = 0; nt < 8; nt++) {
            const __half* wp = &Wt[(warp_n + nt * 8 + group) * FDIM + k0 + t * 2];
            b[nt][0] = *(const unsigned*)wp;
            b[nt][1] = *(const unsigned*)(wp + 8);
        }
        #pragma unroll
        for (int mt = 0; mt < 2; mt++) {
            int r = warp_m + mt * 16 + group;
            unsigned a0 = *(const unsigned*)&As[r][k0 + t * 2];
            unsigned a1 = *(const unsigned*)&As[r + 8][k0 + t * 2];
            unsigned a2 = *(const unsigned*)&As[r][k0 + t * 2 + 8];
            unsigned a3 = *(const unsigned*)&As[r + 8][k0 + t * 2 + 8];
            #pragma unroll
            for (int nt = 0; nt < 8; nt++)
                mma16816(acc[mt][nt], a0, a1, a2, a3, b[nt][0], b[nt][1]);
        }
    }

    // Epilogue: scale by dinv[row], store fp16
    #pragma unroll
    for (int mt = 0; mt < 2; mt++) {
        int rl = row0 + warp_m + mt * 16 + group;
        float dl = (rl < M)     ? g_dinv[rl]     : 0.0f;
        float dh = (rl + 8 < M) ? g_dinv[rl + 8] : 0.0f;
        #pragma unroll
        for (int nt = 0; nt < 8; nt++) {
            int cc = warp_n + nt * 8 + t * 2;
            if (rl < M) {
                __half2 h = __floats2half2_rn(acc[mt][nt][0] * dl, acc[mt][nt][1] * dl);
                *(unsigned*)&C[(long long)rl * FDIM + cc] = *(unsigned*)&h;
            }
            if (rl + 8 < M) {
                __half2 h = __floats2half2_rn(acc[mt][nt][2] * dh, acc[mt][nt][3] * dh);
                *(unsigned*)&C[(long long)(rl + 8) * FDIM + cc] = *(unsigned*)&h;
            }
        }
    }
}

// ---------------- Edge aggregation: half-warp per edge, LDG.128 --------------
__device__ __forceinline__ void addh8(float acc[8], uint4 v) {
    __half2* p = (__half2*)&v;
    #pragma unroll
    for (int q = 0; q < 4; q++) {
        float2 f = __half22float2(p[q]);
        acc[2 * q]     += f.x;
        acc[2 * q + 1] += f.y;
    }
}

__global__ __launch_bounds__(256) void k_gather128(
    const __half* __restrict__ hw, const float* __restrict__ bias,
    __half* __restrict__ out, int N, int do_relu)
{
    int warp = (blockIdx.x * blockDim.x + threadIdx.x) >> 5;
    int lane = threadIdx.x & 31;
    if (warp >= N) return;
    int h  = lane >> 4;          // half-warp id: 0/1
    int sl = lane & 15;          // sub-lane: feature chunk [sl*8, sl*8+8)
    int beg = g_rowptr[warp];
    int end = g_rowptr[warp + 1];

    float acc[8];
    #pragma unroll
    for (int j = 0; j < 8; j++) acc[j] = 0.0f;

    int base = beg;
    for (; base + 8 <= end; base += 8) {
        int s0 = g_srcs[base + h];
        int s1 = g_srcs[base + h + 2];
        int s2 = g_srcs[base + h + 4];
        int s3 = g_srcs[base + h + 6];
        uint4 v0 = *(const uint4*)&hw[(long long)s0 * FDIM + sl * 8];
        uint4 v1 = *(const uint4*)&hw[(long long)s1 * FDIM + sl * 8];
        uint4 v2 = *(const uint4*)&hw[(long long)s2 * FDIM + sl * 8];
        uint4 v3 = *(const uint4*)&hw[(long long)s3 * FDIM + sl * 8];
        addh8(acc, v0); addh8(acc, v1); addh8(acc, v2); addh8(acc, v3);
    }
    for (; base + 4 <= end; base += 4) {
        int s0 = g_srcs[base + h];
        int s1 = g_srcs[base + h + 2];
        uint4 v0 = *(const uint4*)&hw[(long long)s0 * FDIM + sl * 8];
        uint4 v1 = *(const uint4*)&hw[(long long)s1 * FDIM + sl * 8];
        addh8(acc, v0); addh8(acc, v1);
    }
    if (base + h < end) {
        int s = g_srcs[base + h];
        uint4 v = *(const uint4*)&hw[(long long)s * FDIM + sl * 8];
        addh8(acc, v);
    }
    if (base + h + 2 < end) {
        int s = g_srcs[base + h + 2];
        uint4 v = *(const uint4*)&hw[(long long)s * FDIM + sl * 8];
        addh8(acc, v);
    }

    // combine the two half-warps
    #pragma unroll
    for (int j = 0; j < 8; j++) acc[j] += __shfl_xor_sync(0xFFFFFFFFu, acc[j], 16);

    if (h == 0) {
        float d = g_dinv[warp];
        float4 b0 = *(const float4*)&bias[sl * 8];
        float4 b1 = *(const float4*)&bias[sl * 8 + 4];
        float v[8];
        v[0] = fmaf(acc[0], d, b0.x); v[1] = fmaf(acc[1], d, b0.y);
        v[2] = fmaf(acc[2], d, b0.z); v[3] = fmaf(acc[3], d, b0.w);
        v[4] = fmaf(acc[4], d, b1.x); v[5] = fmaf(acc[5], d, b1.y);
        v[6] = fmaf(acc[6], d, b1.z); v[7] = fmaf(acc[7], d, b1.w);
        if (do_relu) {
            #pragma unroll
            for (int j = 0; j < 8; j++) v[j] = fmaxf(v[j], 0.0f);
        }
        __half2 h0 = __floats2half2_rn(v[0], v[1]);
        __half2 h1 = __floats2half2_rn(v[2], v[3]);
        __half2 h2 = __floats2half2_rn(v[4], v[5]);
        __half2 h3 = __floats2half2_rn(v[6], v[7]);
        uint4 u;
        u.x = *(unsigned*)&h0; u.y = *(unsigned*)&h1;
        u.z = *(unsigned*)&h2; u.w = *(unsigned*)&h3;
        *(uint4*)&out[(long long)warp * FDIM + sl * 8] = u;
    }
}

// ---------------- Last layer: fp16 rows, stride 16 (32B = one sector) --------
__device__ __forceinline__ float4 ld_half4(const __half* base, long long s, int lane) {
    uint2 raw = *(const uint2*)&base[s * FDIM + lane * 4];
    __half2 a0 = *(__half2*)&raw.x;
    __half2 a1 = *(__half2*)&raw.y;
    float2 f0 = __half22float2(a0);
    float2 f1 = __half22float2(a1);
    return make_float4(f0.x, f0.y, f1.x, f1.y);
}

__global__ __launch_bounds__(256) void k_gemm10(
    const __half* __restrict__ A, const float* __restrict__ W,
    __half* __restrict__ C, int M)
{
    __shared__ float Ws[128 * 10];
    int tid = threadIdx.x;
    for (int j = tid; j < 1280; j += 256) Ws[j] = W[j];
    __syncthreads();
    int r = blockIdx.x * 8 + (tid >> 5);
    int lane = tid & 31;
    if (r >= M) return;
    float4 a = ld_half4(A, r, lane);
    float acc[10];
    #pragma unroll
    for (int c = 0; c < 10; c++) {
        acc[c] = a.x * Ws[(lane * 4 + 0) * 10 + c]
               + a.y * Ws[(lane * 4 + 1) * 10 + c]
               + a.z * Ws[(lane * 4 + 2) * 10 + c]
               + a.w * Ws[(lane * 4 + 3) * 10 + c];
    }
    #pragma unroll
    for (int off = 16; off > 0; off >>= 1)
        #pragma unroll
        for (int c = 0; c < 10; c++)
            acc[c] += __shfl_xor_sync(0xFFFFFFFFu, acc[c], off);
    float v = 0.0f;
    #pragma unroll
    for (int c = 0; c < 10; c++) v = (lane == c) ? acc[c] : v;
    if (lane < 10) C[(long long)r * 16 + lane] = __float2half(v * g_dinv[r]);
    if (lane >= 10 && lane < 16) C[(long long)r * 16 + lane] = __float2half(0.0f);
}

// 16 edges per warp iteration: 2 lanes per edge (16B each, one 32B sector/edge).
__global__ __launch_bounds__(256) void k_gather10(
    const __half* __restrict__ hw, const float* __restrict__ bias,
    float* __restrict__ out, int N)
{
    int warp = (blockIdx.x * blockDim.x + threadIdx.x) >> 5;
    int lane = threadIdx.x & 31;
    if (warp >= N) return;
    int half = lane & 1;          // which 8-half chunk of the 16-half row
    int eoff = lane >> 1;         // 0..15: edge within batch
    int beg = g_rowptr[warp];
    int end = g_rowptr[warp + 1];

    float acc[8];
    #pragma unroll
    for (int j = 0; j < 8; j++) acc[j] = 0.0f;

    for (int base = beg; base < end; base += 16) {
        int e = base + eoff;
        if (e < end) {
            int s = g_srcs[e];
            uint4 v = *(const uint4*)&hw[(long long)s * 16 + half * 8];
            addh8(acc, v);
        }
    }
    // reduce across the 16 edge slots (parity-preserving strides)
    #pragma unroll
    for (int off = 2; off <= 16; off <<= 1)
        #pragma unroll
        for (int j = 0; j < 8; j++)
            acc[j] += __shfl_xor_sync(0xFFFFFFFFu, acc[j], off);

    // lane0 holds features 0..7, lane1 holds features 8..15 (only 8,9 real)
    if (lane == 0) {
        float d = g_dinv[warp];
        #pragma unroll
        for (int j = 0; j < 8; j++)
            out[(long long)warp * 16 + j] = fmaf(acc[j], d, bias[j]);
    } else if (lane == 1) {
        float d = g_dinv[warp];
        #pragma unroll
        for (int j = 0; j < 2; j++)
            out[(long long)warp * 16 + 8 + j] = fmaf(acc[j], d, bias[8 + j]);
    }
}

// ---------------- Pool (one block per graph) + log_softmax, fused ------------
__global__ __launch_bounds__(128) void k_poolfinal(float* __restrict__ out) {
    int g = blockIdx.x;
    int beg = g_gstart[g], end = g_gstart[g + 1];
    int tid = threadIdx.x;

    float acc[10];
    #pragma unroll
    for (int c = 0; c < 10; c++) acc[c] = 0.0f;
    for (int i = beg + tid; i < end; i += 128) {
        const float* p = &g_h10b[(long long)i * 16];
        #pragma unroll
        for (int c = 0; c < 10; c++) acc[c] += p[c];
    }
    #pragma unroll
    for (int off = 16; off > 0; off >>= 1)
        #pragma unroll
        for (int c = 0; c < 10; c++)
            acc[c] += __shfl_xor_sync(0xFFFFFFFFu, acc[c], off);

    __shared__ float sh[4][10];
    if ((tid & 31) == 0) {
        #pragma unroll
        for (int c = 0; c < 10; c++) sh[tid >> 5][c] = acc[c];
    }
    __syncthreads();
    if (tid == 0) {
        float cnt = fmaxf((float)(end - beg), 1.0f);
        float v[10];
        float m = -1e30f;
        #pragma unroll
        for (int c = 0; c < 10; c++) {
            v[c] = (sh[0][c] + sh[1][c] + sh[2][c] + sh[3][c]) / cnt;
            m = fmaxf(m, v[c]);
        }
        float s = 0.0f;
        #pragma unroll
        for (int c = 0; c < 10; c++) s += __expf(v[c] - m);
        float lse = m + __logf(s);
        #pragma unroll
        for (int c = 0; c < 10; c++) out[g * 10 + c] = v[c] - lse;
    }
}

// ---------------- Launch ----------------
extern "C" void kernel_launch(void* const* d_in, const int* in_sizes, int n_in,
                              void* d_out, int out_size)
{
    const float* x     = (const float*)d_in[0];
    const int*   ei    = (const int*)d_in[1];     // int32
    const int*   batch = (const int*)d_in[2];     // int32
    const float* W_in  = (const float*)d_in[3];
    const float* b_in  = (const float*)d_in[4];
    const float* W_h0  = (const float*)d_in[5];
    const float* b_h0  = (const float*)d_in[6];
    const float* W_h1  = (const float*)d_in[7];
    const float* b_h1  = (const float*)d_in[8];
    const float* W_out = (const float*)d_in[9];
    const float* b_out = (const float*)d_in[10];
    float* out = (float*)d_out;

    int N = in_sizes[0] / FDIM;       // 100000
    int E = in_sizes[1] / 2;          // 3200000

    __half *f16a, *f16b, *Wt, *h10h;
    float *h10b;
    cudaGetSymbolAddress((void**)&f16a, g_f16a);
    cudaGetSymbolAddress((void**)&f16b, g_f16b);
    cudaGetSymbolAddress((void**)&Wt,   g_Wt);
    cudaGetSymbolAddress((void**)&h10h, g_h10h);
    cudaGetSymbolAddress((void**)&h10b, g_h10b);

    int tb = 256;
    int gbN = (N + tb - 1) / tb;
    int gbE = (E + tb - 1) / tb;
    int nb  = (N + 1023) / 1024;

    int gemmBlocks   = (N + 127) / 128;
    int gatherBlocks = (N + 7) / 8;    // 8 warps per 256-thread block

    // Side stream + events for fork-join overlap (capture-safe pattern).
    // Created per call; never destroyed during capture (kernel_launch host code
    // runs only a handful of times — correctness + capture — so no leak issue).
    cudaStream_t s1;
    cudaStreamCreateWithFlags(&s1, cudaStreamNonBlocking);
    cudaEvent_t evFork, evDinv, evG1;
    cudaEventCreateWithFlags(&evFork, cudaEventDisableTiming);
    cudaEventCreateWithFlags(&evDinv, cudaEventDisableTiming);
    cudaEventCreateWithFlags(&evG1,   cudaEventDisableTiming);

    cudaEventRecord(evFork, 0);

    // Main stream: CSR build chain
    k_init<<<gbN, tb>>>(N);
    k_count<<<gbE, tb>>>(ei, E);
    k_dinv<<<gbN, tb>>>(N);
    cudaEventRecord(evDinv, 0);
    k_scan_block<<<nb, 1024>>>(N);
    k_scan_sums<<<1, 128>>>(nb, N);
    k_finalize<<<gbN, tb>>>(N);
    k_fill<<<gbE, tb>>>(ei, E);

    // Side stream: gbound + weight prep (independent), then layer-1 GEMM
    // (needs only x, Wt, dinv) concurrent with scan/fill.
    cudaStreamWaitEvent(s1, evFork, 0);
    k_gbound<<<gbN, tb, 0, s1>>>(batch, N);
    k_prepW3<<<(3 * FDIM * FDIM + 255) / 256, 256, 0, s1>>>(W_in, W_h0, W_h1, Wt);
    cudaStreamWaitEvent(s1, evDinv, 0);
    k_gemmTC<true><<<gemmBlocks, 256, 0, s1>>>(x, Wt, f16b, N);
    cudaEventRecord(evG1, s1);

    // Join: gather-1 needs CSR (main) + layer-1 GEMM (side)
    cudaStreamWaitEvent(0, evG1, 0);

    k_gather128<<<gatherBlocks, 256>>>(f16b, b_in, f16a, N, 1);
    // Layer 2
    k_gemmTC<false><<<gemmBlocks, 256>>>(f16a, Wt + FDIM * FDIM, f16b, N);
    k_gather128<<<gatherBlocks, 256>>>(f16b, b_h0, f16a, N, 1);
    // Layer 3
    k_gemmTC<false><<<gemmBlocks, 256>>>(f16a, Wt + 2 * FDIM * FDIM, f16b, N);
    k_gather128<<<gatherBlocks, 256>>>(f16b, b_h1, f16a, N, 1);
    // Output layer (C=10, no relu), fp16 stride-16 rows
    k_gemm10<<<(N + 7) / 8, 256>>>(f16a, W_out, h10h, N);
    k_gather10<<<gatherBlocks, 256>>>(h10h, b_out, h10b, N);

    // Fused mean-pool + log_softmax (one block per graph)
    k_poolfinal<<<NGRAPH, 128>>>(out);
}